// round 3
// baseline (speedup 1.0000x reference)
#include <cuda_runtime.h>
#include <math.h>

#define N_NODES 10000
#define N_EDGES 64000
#define RHID 64
#define SQM 5.656854249492381f
#define NB 4
#define SMEM_NODE_BYTES 84480

__device__ float g_h[N_NODES * 32];
__device__ float g_rf[N_EDGES * RHID];
__device__ float g_A3[2080 * 96];
__device__ float g_asum[N_NODES * 288];
__device__ float g_cnt[N_NODES];

__device__ int   g_cg_ij[11][160];
__device__ float g_cg_v[11][160];
__device__ int   g_cg_off[11][6];

__constant__ int c_PI[11]   = {0,0,0,1,1,1,1,2,2,2,2};
__constant__ int c_PJ[11]   = {0,1,2,0,1,1,2,0,1,2,2};
__constant__ int c_PK[11]   = {0,1,2,1,0,2,1,2,1,0,2};
__constant__ int c_SOFF[3]  = {0,1,4};
__constant__ int c_LD[3]    = {1,3,5};
__constant__ int c_LSLOT[9] = {0,1,1,1,2,2,2,2,2};
__constant__ int c_O2W[3]   = {1,2,6};
__constant__ int c_O2U[5]   = {0,4,5,9,10};

__device__ __forceinline__ int mergecol(int u, int slot) {
    if (slot == 0) return u;
    if (slot < 4)  return 32 + u * 3 + (slot - 1);
    return 128 + u * 5 + (slot - 4);
}

/* -------------------- CG table init (1 block, warp per combo) ------- */
__global__ void mace_init_cg() {
    __shared__ float C[11][125];
    int w = threadIdx.x >> 5, lane = threadIdx.x & 31;
    if (w >= 11) return;
    const float s2 = sqrtf(2.f), s3 = sqrtf(3.f), s5 = sqrtf(5.f), s6 = sqrtf(6.f);
    float B[5][3][3];
    for (int a = 0; a < 5; a++) for (int i = 0; i < 3; i++) for (int j = 0; j < 3; j++) B[a][i][j] = 0.f;
    B[0][0][1] = B[0][1][0] = 1.f / s2;
    B[1][1][2] = B[1][2][1] = 1.f / s2;
    B[2][0][0] = -1.f / s6; B[2][1][1] = -1.f / s6; B[2][2][2] = 2.f / s6;
    B[3][0][2] = B[3][2][0] = 1.f / s2;
    B[4][0][0] = 1.f / s2;  B[4][1][1] = -1.f / s2;
    int combo = w;
    int di = c_LD[c_PI[combo]], dj = c_LD[c_PJ[combo]], dk = c_LD[c_PK[combo]];
    float* Cc = C[combo];
    for (int t = lane; t < 125; t += 32) Cc[t] = 0.f;
    __syncwarp();
    switch (combo) {
        case 0: if (lane == 0) Cc[0] = 1.f; break;
        case 1: if (lane < 3) Cc[(0 * 5 + lane) * 5 + lane] = 1.f / s3; break;
        case 2: if (lane < 5) Cc[(0 * 5 + lane) * 5 + lane] = 1.f / s5; break;
        case 3: if (lane < 3) Cc[(lane * 5 + 0) * 5 + lane] = 1.f / s3; break;
        case 4: if (lane < 3) Cc[(lane * 5 + lane) * 5 + 0] = 1.f / s3; break;
        case 5: for (int t = lane; t < 45; t += 32) { int i = t / 15, j = (t % 15) / 5, k = t % 5;
                    Cc[(i * 5 + j) * 5 + k] = B[k][i][j] / s5; } break;
        case 6: for (int t = lane; t < 45; t += 32) { int i = t / 15, j = (t % 15) / 3, k = t % 3;
                    Cc[(i * 5 + j) * 5 + k] = B[j][i][k] / s5; } break;
        case 7: if (lane < 5) Cc[(lane * 5 + 0) * 5 + lane] = 1.f / s5; break;
        case 8: for (int t = lane; t < 45; t += 32) { int i = t / 9, j = (t % 9) / 3, k = t % 3;
                    Cc[(i * 5 + j) * 5 + k] = B[i][j][k] / s5; } break;
        case 9: if (lane < 5) Cc[(lane * 5 + lane) * 5 + 0] = 1.f / s5; break;
        case 10: {
            float ss = 0.f;
            for (int t = lane; t < 125; t += 32) {
                int a = t / 25, b = (t % 25) / 5, c = t % 5;
                float s = 0.f;
                for (int i = 0; i < 3; i++) for (int j = 0; j < 3; j++) for (int k = 0; k < 3; k++)
                    s += B[a][i][j] * B[b][j][k] * B[c][k][i];
                Cc[(a * 5 + b) * 5 + c] = s; ss += s * s;
            }
            for (int o = 16; o; o >>= 1) ss += __shfl_xor_sync(0xffffffff, ss, o);
            float rn = 1.f / sqrtf(ss);
            __syncwarp();
            for (int t = lane; t < 125; t += 32) Cc[t] *= rn;
        } break;
    }
    __syncwarp();
    if (lane == 0) {
        int pos = 0;
        for (int kk = 0; kk < dk; kk++) {
            g_cg_off[combo][kk] = pos;
            for (int ii = 0; ii < di; ii++) for (int jj = 0; jj < dj; jj++) {
                float v = Cc[(ii * 5 + jj) * 5 + kk];
                if (v != 0.f) { g_cg_ij[combo][pos] = ii * 16 + jj; g_cg_v[combo][pos] = v; pos++; }
            }
        }
        g_cg_off[combo][dk] = pos;
    }
}

/* -------------------- repack edge-GEMM B matrix --------------------- */
__global__ void mace_init_A3(const float* __restrict__ aw, const float* __restrict__ ab) {
    int idx = blockIdx.x * blockDim.x + threadIdx.x;
    if (idx >= 2080 * 96) return;
    int k = idx / 96, n = idx - k * 96;
    int l = n >> 5, ww = n & 31;
    const float rsd[3] = {1.f, 0.57735026918962576f, 0.44721359549995794f};
    float scale = rsd[l] * (1.f / SQM);
    float v;
    if (k < 2048) { int r = k >> 5, u = k & 31; v = aw[r * 3072 + l * 1024 + u * 32 + ww]; }
    else          { int u = k - 2048;           v = ab[l * 1024 + u * 32 + ww]; }
    g_A3[idx] = v * scale;
}

__global__ void mace_zero() {
    int i = blockIdx.x * blockDim.x + threadIdx.x;
    if (i < N_NODES * 288) g_asum[i] = 0.f;
    if (i < N_NODES)       g_cnt[i]  = 0.f;
}

__global__ void mace_h(const float* __restrict__ nf, const float* __restrict__ emb) {
    int z = blockIdx.x * 8 + (threadIdx.x >> 5);
    int ww = threadIdx.x & 31;
    const float* r = nf + z * 32;
    float s = 0.f;
#pragma unroll 8
    for (int u = 0; u < 32; u++) s += r[u] * emb[u * 32 + ww];
    g_h[z * 32 + ww] = s * (1.f / SQM);
}

/* -------------------- edge radial MLP ------------------------------- */
__global__ __launch_bounds__(512) void mace_mlp(
    const int* __restrict__ ei, const float* __restrict__ rad, const float* __restrict__ attr,
    const float* __restrict__ w1, const float* __restrict__ b1,
    const float* __restrict__ w2, const float* __restrict__ b2,
    const float* __restrict__ w3, const float* __restrict__ b3) {
    __shared__ float w1s[24 * 64], w2s[64 * 64], w3s[64 * 64];
    __shared__ float b1s[64], b2s[64], b3s[64];
    __shared__ float rin[8][24], x1[8][64], x2[8][64];
    int tid = threadIdx.x;
    for (int i = tid; i < 1536; i += 512) w1s[i] = w1[i];
    for (int i = tid; i < 4096; i += 512) { w2s[i] = w2[i]; w3s[i] = w3[i]; }
    if (tid < 64) { b1s[tid] = b1[tid]; b2s[tid] = b2[tid]; b3s[tid] = b3[tid]; }
    int eg = tid >> 6, t = tid & 63;
    int e = blockIdx.x * 8 + eg;
    if (t < 8)       rin[eg][t] = rad[e * 8 + t];
    else if (t < 24) rin[eg][t] = attr[e * 16 + (t - 8)];
    __syncthreads();
    float s = b1s[t];
#pragma unroll
    for (int k = 0; k < 24; k++) s += rin[eg][k] * w1s[k * 64 + t];
    s = s / (1.f + expf(-s));
    x1[eg][t] = s;
    __syncthreads();
    s = b2s[t];
#pragma unroll 8
    for (int k = 0; k < 64; k++) s += x1[eg][k] * w2s[k * 64 + t];
    s = s / (1.f + expf(-s));
    x2[eg][t] = s;
    __syncthreads();
    s = b3s[t];
#pragma unroll 8
    for (int k = 0; k < 64; k++) s += x2[eg][k] * w3s[k * 64 + t];
    g_rf[e * 64 + t] = s;
    if (t == 0) atomicAdd(&g_cnt[ei[N_EDGES + e]], 1.f);
}

/* ------------ fused edge GEMM + SH expand + atomic scatter ---------- */
__global__ __launch_bounds__(256) void mace_edge_gemm(
    const int* __restrict__ ei, const float* __restrict__ sh) {
    __shared__ int s_src[64], s_dst[64];
    __shared__ float s_sh[64 * 9];
    __shared__ float Hs[64 * 33];
    __shared__ float RFs[64 * 64];
    __shared__ float At[32 * 96];
    int tid = threadIdx.x;
    int e0 = blockIdx.x * 64;
    for (int i = tid; i < 64; i += 256) { s_src[i] = ei[e0 + i]; s_dst[i] = ei[N_EDGES + e0 + i]; }
    for (int i = tid; i < 576; i += 256) s_sh[i] = sh[e0 * 9 + i];
    __syncthreads();
    for (int i = tid; i < 2048; i += 256) { int e = i >> 5, u = i & 31; Hs[e * 33 + u] = g_h[s_src[e] * 32 + u]; }
    for (int i = tid; i < 4096; i += 256) { int e = i >> 6, r = i & 63; RFs[e * 64 + r] = g_rf[(e0 + e) * 64 + r]; }
    int tx = tid & 31, ty = tid >> 5;
    float acc[8][3];
#pragma unroll
    for (int i = 0; i < 8; i++) { acc[i][0] = 0.f; acc[i][1] = 0.f; acc[i][2] = 0.f; }

    for (int kc = 0; kc < 2080; kc += 32) {
        __syncthreads();
        for (int i = tid; i < 3072; i += 256) {
            int kk = i / 96, n = i - kk * 96;
            At[i] = g_A3[(kc + kk) * 96 + n];
        }
        __syncthreads();
        bool bias = (kc >= 2048);
        int r = kc >> 5;
        float rfv[8];
#pragma unroll
        for (int i = 0; i < 8; i++) {
            rfv[i] = 1.f;
            if (!bias) rfv[i] = RFs[(ty * 8 + i) * 64 + r];
        }
#pragma unroll 4
        for (int kk = 0; kk < 32; kk++) {
            float a0 = At[kk * 96 + tx], a1 = At[kk * 96 + 32 + tx], a2 = At[kk * 96 + 64 + tx];
#pragma unroll
            for (int i = 0; i < 8; i++) {
                int e = ty * 8 + i;
                float p = rfv[i] * Hs[e * 33 + kk];
                acc[i][0] += p * a0; acc[i][1] += p * a1; acc[i][2] += p * a2;
            }
        }
    }
    __syncthreads();
#pragma unroll
    for (int i = 0; i < 8; i++) {
        int e = ty * 8 + i;
        float* ob = &g_asum[s_dst[e] * 288];
        const float* shv = &s_sh[e * 9];
        atomicAdd(ob + tx, acc[i][0] * shv[0]);
        float m1 = acc[i][1];
#pragma unroll
        for (int q = 0; q < 3; q++) atomicAdd(ob + 32 + tx * 3 + q, m1 * shv[1 + q]);
        float m2 = acc[i][2];
#pragma unroll
        for (int q = 0; q < 5; q++) atomicAdd(ob + 128 + tx * 5 + q, m2 * shv[4 + q]);
    }
}

/* -------------------- per-node CG machinery (NB nodes/block) -------- */
template<int DK>
__device__ void path_pair_multi(const float* __restrict__ x, const float* __restrict__ y,
                                const float* __restrict__ Wp, int combo, float* out, float scale,
                                float* sT, float* sRed, int tid) {
    int i = c_PI[combo], j = c_PJ[combo], k = c_PK[combo];
    int ib = c_SOFF[i], jb = c_SOFF[j], kb = c_SOFF[k];
    int g = tid >> 5, w = tid & 31;
    float part[NB][DK];
#pragma unroll
    for (int n = 0; n < NB; n++)
#pragma unroll
        for (int kk = 0; kk < DK; kk++) part[n][kk] = 0.f;

    for (int h = 0; h < 2; h++) {
        __syncthreads();
        /* stage 1: T for uv in [h*512, h*512+512) */
#pragma unroll
        for (int n = 0; n < NB; n++) {
            const float* xb = x + n * 288;
            const float* yb = y + n * 288;
            for (int uvl = tid; uvl < 512; uvl += 256) {
                int uv = h * 512 + uvl;
                int u = uv >> 5, v = uv & 31;
                const float* xr = xb + u * 9 + ib;
                const float* yr = yb + v * 9 + jb;
#pragma unroll
                for (int kk = 0; kk < DK; kk++) {
                    int s = g_cg_off[combo][kk], e = g_cg_off[combo][kk + 1];
                    float acc = 0.f;
                    for (int t = s; t < e; t++) {
                        int ij = g_cg_ij[combo][t];
                        acc += xr[ij >> 4] * yr[ij & 15] * g_cg_v[combo][t];
                    }
                    sT[(n * DK + kk) * 512 + uvl] = acc;
                }
            }
        }
        __syncthreads();
        /* stage 2: warp g handles 64 uv; W loads coalesced; T broadcast LDS */
        const float* Wg = Wp + (h * 512 + g * 64) * 32 + w;
#pragma unroll 2
        for (int q = 0; q < 64; q += 4) {
            float w0 = __ldg(Wg + q * 32),      w1 = __ldg(Wg + q * 32 + 32);
            float w2 = __ldg(Wg + q * 32 + 64), w3 = __ldg(Wg + q * 32 + 96);
            int base = g * 64 + q;
#pragma unroll
            for (int n = 0; n < NB; n++)
#pragma unroll
                for (int kk = 0; kk < DK; kk++) {
                    float4 tv = *(const float4*)&sT[(n * DK + kk) * 512 + base];
                    part[n][kk] += tv.x * w0 + tv.y * w1 + tv.z * w2 + tv.w * w3;
                }
        }
    }
    const int stride = NB * 32 * DK;
#pragma unroll
    for (int n = 0; n < NB; n++)
#pragma unroll
        for (int kk = 0; kk < DK; kk++) sRed[g * stride + (n * 32 + w) * DK + kk] = part[n][kk];
    __syncthreads();
    for (int o = tid; o < stride; o += 256) {
        int kk = o % DK, nw = o / DK;
        int n = nw >> 5, w2_ = nw & 31;
        float s = 0.f;
#pragma unroll
        for (int g2 = 0; g2 < 8; g2++) s += sRed[g2 * stride + o];
        out[n * 288 + w2_ * 9 + kb + kk] += s * scale;
    }
}

__device__ void path_uvu_multi(const float* __restrict__ x, const float* __restrict__ Wp,
                               int combo, float* out, float* sT, int tid) {
    int i = c_PI[combo], j = c_PJ[combo], k = c_PK[combo];
    int dk = c_LD[k], ib = c_SOFF[i], jb = c_SOFF[j], kb = c_SOFF[k];
    for (int h = 0; h < 2; h++) {
        __syncthreads();
        for (int n = 0; n < NB; n++) {
            const float* xb = x + n * 288;
            for (int uvl = tid; uvl < 512; uvl += 256) {
                int uv = h * 512 + uvl;
                int u = uv >> 5, v = uv & 31;
                const float* xr = xb + u * 9 + ib;
                const float* yr = xb + v * 9 + jb;
                for (int kk = 0; kk < dk; kk++) {
                    int s = g_cg_off[combo][kk], e = g_cg_off[combo][kk + 1];
                    float acc = 0.f;
                    for (int t = s; t < e; t++) {
                        int ij = g_cg_ij[combo][t];
                        acc += xr[ij >> 4] * yr[ij & 15] * g_cg_v[combo][t];
                    }
                    sT[(n * dk + kk) * 512 + uvl] = acc;
                }
            }
        }
        __syncthreads();
        if (tid < 128) {
            int ul = tid >> 3, kk = tid & 7;
            int u = h * 16 + ul;
            if (kk < dk) {
                const float* Wr = Wp + u * 32;
                for (int n = 0; n < NB; n++) {
                    float s = 0.f;
#pragma unroll 8
                    for (int v = 0; v < 32; v++)
                        s += sT[(n * dk + kk) * 512 + ul * 32 + v] * __ldg(Wr + v);
                    out[n * 288 + u * 9 + kb + kk] += s * (1.f / SQM);
                }
            }
        }
    }
}

__device__ __forceinline__ void run_path_multi(const float* x, const float* y, const float* W,
                                               int combo, float* out, float scale,
                                               float* sT, float* sRed, int tid) {
    int dk = c_LD[c_PK[combo]];
    if (dk == 1)      path_pair_multi<1>(x, y, W, combo, out, scale, sT, sRed, tid);
    else if (dk == 3) path_pair_multi<3>(x, y, W, combo, out, scale, sT, sRed, tid);
    else              path_pair_multi<5>(x, y, W, combo, out, scale, sT, sRed, tid);
}

__device__ void lin_multi(const float* in, const float* __restrict__ W, float* out, bool accum, int tid) {
    for (int o = tid; o < NB * 288; o += 256) {
        int n = o / 288, idx = o - n * 288;
        int ww = idx / 9, slot = idx - ww * 9;
        int l = c_LSLOT[slot];
        const float* Wl = W + l * 1024 + ww;
        const float* ib = in + n * 288;
        float s = 0.f;
#pragma unroll 8
        for (int u = 0; u < 32; u++) s += ib[u * 9 + slot] * __ldg(Wl + u * 32);
        s *= (1.f / SQM);
        if (accum) out[o] += s; else out[o] = s;
    }
}

/* -------------------- per-node main kernel (NB nodes/block) --------- */
__global__ __launch_bounds__(256) void mace_node(
    const float* __restrict__ nf, const float* __restrict__ lin_o1,
    const float* __restrict__ o2w, const float* __restrict__ o2u,
    const float* __restrict__ o3a, const float* __restrict__ o3b,
    const float* __restrict__ mixw, const float* __restrict__ combw,
    const float* __restrict__ selfw, float* __restrict__ out) {
    extern __shared__ float smem[];
    float* sa   = smem;                 /* NB*288 */
    float* sbuf = sa + NB * 288;
    float* st2  = sbuf + NB * 288;
    float* smix = st2 + NB * 288;
    float* smsg = smix + NB * 288;
    float* sT   = smsg + NB * 288;      /* NB*5*512 */
    float* sRed = sT + NB * 5 * 512;    /* 8*NB*32*5 */
    int z0 = blockIdx.x * NB, tid = threadIdx.x;

    for (int o = tid; o < NB * 288; o += 256) {
        int n = o / 288, idx = o - n * 288;
        int u = idx / 9, slot = idx - u * 9;
        float inv = 1.f / fmaxf(g_cnt[z0 + n], 1.f);
        sa[o] = g_asum[(z0 + n) * 288 + mergecol(u, slot)] * inv;
        smsg[o] = 0.f;
    }
    __syncthreads();
    /* order 0 */
    lin_multi(sa, lin_o1, sbuf, false, tid); __syncthreads();
    lin_multi(sbuf, mixw, smix, false, tid); __syncthreads();
    lin_multi(smix, combw, smsg, true, tid); __syncthreads();
    /* order 1 */
    for (int o = tid; o < NB * 288; o += 256) sbuf[o] = 0.f;
    for (int p = 0; p < 3; p++)
        run_path_multi(sa, sa, o2w + p * 32768, c_O2W[p], sbuf, 1.f / 32.f, sT, sRed, tid);
    for (int p = 0; p < 5; p++)
        path_uvu_multi(sa, o2u + p * 1024, c_O2U[p], sbuf, sT, tid);
    __syncthreads();
    lin_multi(sbuf, mixw + 3072, smix, false, tid); __syncthreads();
    lin_multi(smix, combw + 3072, smsg, true, tid); __syncthreads();
    /* order 2 */
    for (int o = tid; o < NB * 288; o += 256) st2[o] = 0.f;
    for (int p = 0; p < 11; p++)
        run_path_multi(sa, sa, o3a + p * 32768, p, st2, 1.f / 32.f, sT, sRed, tid);
    __syncthreads();
    for (int o = tid; o < NB * 288; o += 256) sbuf[o] = 0.f;
    for (int p = 0; p < 11; p++)
        run_path_multi(st2, sa, o3b + p * 32768, p, sbuf, 1.f / 32.f, sT, sRed, tid);
    __syncthreads();
    lin_multi(sbuf, mixw + 6144, smix, false, tid); __syncthreads();
    lin_multi(smix, combw + 6144, smsg, true, tid); __syncthreads();
    /* self interaction */
    if (tid < NB * 32) {
        int n = tid >> 5, w = tid & 31;
        const float* r = nf + (z0 + n) * 32;
        float s = 0.f;
#pragma unroll 8
        for (int v = 0; v < 32; v++) s += r[v] * __ldg(selfw + v * 32 + w);
        smsg[n * 288 + w * 9] += s * (1.f / SQM);
    }
    __syncthreads();
    for (int o = tid; o < NB * 288; o += 256) {
        int n = o / 288, idx = o - n * 288;
        int u = idx / 9, slot = idx - u * 9;
        out[(z0 + n) * 288 + mergecol(u, slot)] = smsg[o];
    }
}

/* -------------------- launch ---------------------------------------- */
extern "C" void kernel_launch(void* const* d_in, const int* in_sizes, int n_in,
                              void* d_out, int out_size) {
    const float* nf    = (const float*)d_in[0];
    const int*   ei    = (const int*)d_in[1];
    const float* sh    = (const float*)d_in[2];
    const float* rad   = (const float*)d_in[3];
    const float* attr  = (const float*)d_in[4];
    const float* w1    = (const float*)d_in[5];
    const float* b1    = (const float*)d_in[6];
    const float* w2    = (const float*)d_in[7];
    const float* b2    = (const float*)d_in[8];
    const float* w3    = (const float*)d_in[9];
    const float* b3    = (const float*)d_in[10];
    const float* aw    = (const float*)d_in[11];
    const float* ab    = (const float*)d_in[12];
    const float* emb   = (const float*)d_in[13];
    const float* lino1 = (const float*)d_in[14];
    const float* o2w   = (const float*)d_in[15];
    const float* o2u   = (const float*)d_in[16];
    const float* o3a   = (const float*)d_in[17];
    const float* o3b   = (const float*)d_in[18];
    const float* mixw  = (const float*)d_in[19];
    const float* combw = (const float*)d_in[20];
    const float* selfw = (const float*)d_in[21];

    cudaFuncSetAttribute(mace_node, cudaFuncAttributeMaxDynamicSharedMemorySize, SMEM_NODE_BYTES);

    mace_init_cg<<<1, 352>>>();
    mace_init_A3<<<(2080 * 96 + 255) / 256, 256>>>(aw, ab);
    mace_zero<<<(N_NODES * 288 + 255) / 256, 256>>>();
    mace_h<<<N_NODES / 8, 256>>>(nf, emb);
    mace_mlp<<<N_EDGES / 8, 512>>>(ei, rad, attr, w1, b1, w2, b2, w3, b3);
    mace_edge_gemm<<<N_EDGES / 64, 256>>>(ei, sh);
    mace_node<<<N_NODES / NB, 256, SMEM_NODE_BYTES>>>(nf, lino1, o2w, o2u, o3a, o3b,
                                                      mixw, combw, selfw, (float*)d_out);
}

// round 5
// speedup vs baseline: 1.7213x; 1.7213x over previous
#include <cuda_runtime.h>
#include <math.h>

#define N_NODES 10000
#define N_EDGES 64000
#define RHID 64
#define SQM 5.656854249492381f
#define NB 2
#define SMEM_NODE_BYTES 62720

__device__ float g_h[N_NODES * 32];
__device__ float g_rf[N_EDGES * RHID];
__device__ float g_A3[2080 * 96];
__device__ float g_asum[N_NODES * 288];
__device__ float g_cnt[N_NODES];

/* ----------------- hardcoded Clebsch-Gordan tables ------------------ */
#define R3f   0.57735026918962576f
#define R5f   0.44721359549995794f
#define R10f  0.31622776601683794f
#define R30f  0.18257418583505536f
#define R30x2 0.36514837167011072f
#define CNA   0.20701966780270626f   /* sqrt(12/35)/(2*sqrt(2)) */
#define CNB   0.23904572186687872f   /* sqrt(12/35)/sqrt(6)     */
#define CNC   0.11952286093343936f   /* sqrt(12/35)/(2*sqrt(6)) */

template<int N> struct IC { static constexpr int v = N; };
#define T3(i,j,k,val) f(IC<i>{}, IC<j>{}, IC<k>{}, val)

template<int C> struct CGT;
template<> struct CGT<0> { static constexpr int DK=1,IB=0,JB=0,KB=0;
  template<class F> __device__ static void terms(F f){ T3(0,0,0,1.f); } };
template<> struct CGT<1> { static constexpr int DK=3,IB=0,JB=1,KB=1;
  template<class F> __device__ static void terms(F f){
    T3(0,0,0,R3f); T3(0,1,1,R3f); T3(0,2,2,R3f); } };
template<> struct CGT<2> { static constexpr int DK=5,IB=0,JB=4,KB=4;
  template<class F> __device__ static void terms(F f){
    T3(0,0,0,R5f); T3(0,1,1,R5f); T3(0,2,2,R5f); T3(0,3,3,R5f); T3(0,4,4,R5f); } };
template<> struct CGT<3> { static constexpr int DK=3,IB=1,JB=0,KB=1;
  template<class F> __device__ static void terms(F f){
    T3(0,0,0,R3f); T3(1,0,1,R3f); T3(2,0,2,R3f); } };
template<> struct CGT<4> { static constexpr int DK=1,IB=1,JB=1,KB=0;
  template<class F> __device__ static void terms(F f){
    T3(0,0,0,R3f); T3(1,1,0,R3f); T3(2,2,0,R3f); } };
template<> struct CGT<5> { static constexpr int DK=5,IB=1,JB=1,KB=4;
  template<class F> __device__ static void terms(F f){
    T3(0,1,0,R10f); T3(1,0,0,R10f); T3(1,2,1,R10f); T3(2,1,1,R10f);
    T3(0,0,2,-R30f); T3(1,1,2,-R30f); T3(2,2,2,R30x2);
    T3(0,2,3,R10f); T3(2,0,3,R10f); T3(0,0,4,R10f); T3(1,1,4,-R10f); } };
template<> struct CGT<6> { static constexpr int DK=3,IB=1,JB=4,KB=1;
  template<class F> __device__ static void terms(F f){
    T3(0,0,1,R10f); T3(1,0,0,R10f); T3(1,1,2,R10f); T3(2,1,1,R10f);
    T3(0,2,0,-R30f); T3(1,2,1,-R30f); T3(2,2,2,R30x2);
    T3(0,3,2,R10f); T3(2,3,0,R10f); T3(0,4,0,R10f); T3(1,4,1,-R10f); } };
template<> struct CGT<7> { static constexpr int DK=5,IB=4,JB=0,KB=4;
  template<class F> __device__ static void terms(F f){
    T3(0,0,0,R5f); T3(1,0,1,R5f); T3(2,0,2,R5f); T3(3,0,3,R5f); T3(4,0,4,R5f); } };
template<> struct CGT<8> { static constexpr int DK=3,IB=4,JB=1,KB=1;
  template<class F> __device__ static void terms(F f){
    T3(0,0,1,R10f); T3(0,1,0,R10f); T3(1,1,2,R10f); T3(1,2,1,R10f);
    T3(2,0,0,-R30f); T3(2,1,1,-R30f); T3(2,2,2,R30x2);
    T3(3,0,2,R10f); T3(3,2,0,R10f); T3(4,0,0,R10f); T3(4,1,1,-R10f); } };
template<> struct CGT<9> { static constexpr int DK=1,IB=4,JB=4,KB=0;
  template<class F> __device__ static void terms(F f){
    T3(0,0,0,R5f); T3(1,1,0,R5f); T3(2,2,0,R5f); T3(3,3,0,R5f); T3(4,4,0,R5f); } };
template<> struct CGT<10> { static constexpr int DK=5,IB=4,JB=4,KB=4;
  template<class F> __device__ static void terms(F f){
    T3(0,1,3,CNA); T3(0,3,1,CNA); T3(1,0,3,CNA); T3(1,3,0,CNA); T3(3,0,1,CNA); T3(3,1,0,CNA);
    T3(0,0,2,-CNB); T3(0,2,0,-CNB); T3(2,0,0,-CNB);
    T3(1,1,2,CNC); T3(1,2,1,CNC); T3(2,1,1,CNC);
    T3(3,3,2,CNC); T3(3,2,3,CNC); T3(2,3,3,CNC);
    T3(1,1,4,-CNA); T3(1,4,1,-CNA); T3(4,1,1,-CNA);
    T3(3,3,4,CNA); T3(3,4,3,CNA); T3(4,3,3,CNA);
    T3(2,2,2,CNB);
    T3(2,4,4,-CNB); T3(4,2,4,-CNB); T3(4,4,2,-CNB); } };

__constant__ int c_LSLOT[9] = {0,1,1,1,2,2,2,2,2};

__device__ __forceinline__ int mergecol(int u, int slot) {
    if (slot == 0) return u;
    if (slot < 4)  return 32 + u * 3 + (slot - 1);
    return 128 + u * 5 + (slot - 4);
}

/* -------------------- repack edge-GEMM B matrix --------------------- */
__global__ void mace_init_A3(const float* __restrict__ aw, const float* __restrict__ ab) {
    int idx = blockIdx.x * blockDim.x + threadIdx.x;
    if (idx >= 2080 * 96) return;
    int k = idx / 96, n = idx - k * 96;
    int l = n >> 5, ww = n & 31;
    const float rsd[3] = {1.f, 0.57735026918962576f, 0.44721359549995794f};
    float scale = rsd[l] * (1.f / SQM);
    float v;
    if (k < 2048) { int r = k >> 5, u = k & 31; v = aw[r * 3072 + l * 1024 + u * 32 + ww]; }
    else          { int u = k - 2048;           v = ab[l * 1024 + u * 32 + ww]; }
    g_A3[idx] = v * scale;
}

__global__ void mace_zero() {
    int i = blockIdx.x * blockDim.x + threadIdx.x;
    if (i < N_NODES * 288) g_asum[i] = 0.f;
    if (i < N_NODES)       g_cnt[i]  = 0.f;
}

__global__ void mace_h(const float* __restrict__ nf, const float* __restrict__ emb) {
    int z = blockIdx.x * 8 + (threadIdx.x >> 5);
    int ww = threadIdx.x & 31;
    const float* r = nf + z * 32;
    float s = 0.f;
#pragma unroll 8
    for (int u = 0; u < 32; u++) s += r[u] * emb[u * 32 + ww];
    g_h[z * 32 + ww] = s * (1.f / SQM);
}

/* -------------------- edge radial MLP ------------------------------- */
__global__ __launch_bounds__(512) void mace_mlp(
    const int* __restrict__ ei, const float* __restrict__ rad, const float* __restrict__ attr,
    const float* __restrict__ w1, const float* __restrict__ b1,
    const float* __restrict__ w2, const float* __restrict__ b2,
    const float* __restrict__ w3, const float* __restrict__ b3) {
    __shared__ float w1s[24 * 64], w2s[64 * 64], w3s[64 * 64];
    __shared__ float b1s[64], b2s[64], b3s[64];
    __shared__ float rin[8][24], x1[8][64], x2[8][64];
    int tid = threadIdx.x;
    for (int i = tid; i < 1536; i += 512) w1s[i] = w1[i];
    for (int i = tid; i < 4096; i += 512) { w2s[i] = w2[i]; w3s[i] = w3[i]; }
    if (tid < 64) { b1s[tid] = b1[tid]; b2s[tid] = b2[tid]; b3s[tid] = b3[tid]; }
    int eg = tid >> 6, t = tid & 63;
    int e = blockIdx.x * 8 + eg;
    if (t < 8)       rin[eg][t] = rad[e * 8 + t];
    else if (t < 24) rin[eg][t] = attr[e * 16 + (t - 8)];
    __syncthreads();
    float s = b1s[t];
#pragma unroll
    for (int k = 0; k < 24; k++) s += rin[eg][k] * w1s[k * 64 + t];
    s = s / (1.f + expf(-s));
    x1[eg][t] = s;
    __syncthreads();
    s = b2s[t];
#pragma unroll 8
    for (int k = 0; k < 64; k++) s += x1[eg][k] * w2s[k * 64 + t];
    s = s / (1.f + expf(-s));
    x2[eg][t] = s;
    __syncthreads();
    s = b3s[t];
#pragma unroll 8
    for (int k = 0; k < 64; k++) s += x2[eg][k] * w3s[k * 64 + t];
    g_rf[e * 64 + t] = s;
    if (t == 0) atomicAdd(&g_cnt[ei[N_EDGES + e]], 1.f);
}

/* ------------ fused edge GEMM + SH expand + atomic scatter ---------- */
__global__ __launch_bounds__(256) void mace_edge_gemm(
    const int* __restrict__ ei, const float* __restrict__ sh) {
    __shared__ int s_src[64], s_dst[64];
    __shared__ float s_sh[64 * 9];
    __shared__ float Hs[64 * 33];
    __shared__ float RFs[64 * 64];
    __shared__ float At[32 * 96];
    int tid = threadIdx.x;
    int e0 = blockIdx.x * 64;
    for (int i = tid; i < 64; i += 256) { s_src[i] = ei[e0 + i]; s_dst[i] = ei[N_EDGES + e0 + i]; }
    for (int i = tid; i < 576; i += 256) s_sh[i] = sh[e0 * 9 + i];
    __syncthreads();
    for (int i = tid; i < 2048; i += 256) { int e = i >> 5, u = i & 31; Hs[e * 33 + u] = g_h[s_src[e] * 32 + u]; }
    for (int i = tid; i < 4096; i += 256) { int e = i >> 6, r = i & 63; RFs[e * 64 + r] = g_rf[(e0 + e) * 64 + r]; }
    int tx = tid & 31, ty = tid >> 5;
    float acc[8][3];
#pragma unroll
    for (int i = 0; i < 8; i++) { acc[i][0] = 0.f; acc[i][1] = 0.f; acc[i][2] = 0.f; }

    for (int kc = 0; kc < 2080; kc += 32) {
        __syncthreads();
        for (int i = tid; i < 3072; i += 256) {
            int kk = i / 96, n = i - kk * 96;
            At[i] = g_A3[(kc + kk) * 96 + n];
        }
        __syncthreads();
        bool bias = (kc >= 2048);
        int r = kc >> 5;
        float rfv[8];
#pragma unroll
        for (int i = 0; i < 8; i++) {
            rfv[i] = 1.f;
            if (!bias) rfv[i] = RFs[(ty * 8 + i) * 64 + r];
        }
#pragma unroll 4
        for (int kk = 0; kk < 32; kk++) {
            float a0 = At[kk * 96 + tx], a1 = At[kk * 96 + 32 + tx], a2 = At[kk * 96 + 64 + tx];
#pragma unroll
            for (int i = 0; i < 8; i++) {
                int e = ty * 8 + i;
                float p = rfv[i] * Hs[e * 33 + kk];
                acc[i][0] += p * a0; acc[i][1] += p * a1; acc[i][2] += p * a2;
            }
        }
    }
    __syncthreads();
#pragma unroll
    for (int i = 0; i < 8; i++) {
        int e = ty * 8 + i;
        float* ob = &g_asum[s_dst[e] * 288];
        const float* shv = &s_sh[e * 9];
        atomicAdd(ob + tx, acc[i][0] * shv[0]);
        float m1 = acc[i][1];
#pragma unroll
        for (int q = 0; q < 3; q++) atomicAdd(ob + 32 + tx * 3 + q, m1 * shv[1 + q]);
        float m2 = acc[i][2];
#pragma unroll
        for (int q = 0; q < 5; q++) atomicAdd(ob + 128 + tx * 5 + q, m2 * shv[4 + q]);
    }
}

/* -------------------- per-node CG machinery (NB=2) ------------------ */
template<int C>
__device__ __forceinline__ void stage1(const float* __restrict__ x, const float* __restrict__ y,
                                       float* __restrict__ sT, int tid) {
    constexpr int DK = CGT<C>::DK;
#pragma unroll
    for (int rep = 0; rep < NB * 4; rep++) {
        int idx = rep * 256 + tid;
        int n = idx >> 10, uv = idx & 1023;
        int u = uv >> 5, v = uv & 31;
        const float* xr = x + n * 288 + u * 9 + CGT<C>::IB;
        const float* yr = y + n * 288 + v * 9 + CGT<C>::JB;
        float acc[DK];
#pragma unroll
        for (int kk = 0; kk < DK; kk++) acc[kk] = 0.f;
        CGT<C>::terms([&](auto ti, auto tj, auto tk, float val) {
            acc[tk.v] = fmaf(xr[ti.v] * yr[tj.v], val, acc[tk.v]);
        });
#pragma unroll
        for (int kk = 0; kk < DK; kk++) sT[(n * DK + kk) * 1024 + uv] = acc[kk];
    }
}

template<int C>
__device__ void path_pair2(const float* __restrict__ x, const float* __restrict__ y,
                           const float* __restrict__ Wp, float* __restrict__ out,
                           float* __restrict__ sT, float* __restrict__ sRed, int tid) {
    constexpr int DK = CGT<C>::DK;
    constexpr int STRIDE = NB * 32 * DK;
    stage1<C>(x, y, sT, tid);
    __syncthreads();
    int g = tid >> 5, w = tid & 31;
    float part[NB][DK];
#pragma unroll
    for (int n = 0; n < NB; n++)
#pragma unroll
        for (int kk = 0; kk < DK; kk++) part[n][kk] = 0.f;
    const float* Wg = Wp + g * 128 * 32 + w;
#pragma unroll 2
    for (int q = 0; q < 128; q += 4) {
        float w0 = __ldg(Wg + q * 32),      w1 = __ldg(Wg + q * 32 + 32);
        float w2 = __ldg(Wg + q * 32 + 64), w3 = __ldg(Wg + q * 32 + 96);
        int base = g * 128 + q;
#pragma unroll
        for (int n = 0; n < NB; n++)
#pragma unroll
            for (int kk = 0; kk < DK; kk++) {
                float4 tv = *(const float4*)&sT[(n * DK + kk) * 1024 + base];
                part[n][kk] += tv.x * w0 + tv.y * w1 + tv.z * w2 + tv.w * w3;
            }
    }
#pragma unroll
    for (int n = 0; n < NB; n++)
#pragma unroll
        for (int kk = 0; kk < DK; kk++) sRed[g * STRIDE + (n * 32 + w) * DK + kk] = part[n][kk];
    __syncthreads();
    for (int o = tid; o < STRIDE; o += 256) {
        int kk = o % DK, nw = o / DK;
        int n = nw >> 5, w2_ = nw & 31;
        float s = 0.f;
#pragma unroll
        for (int g2 = 0; g2 < 8; g2++) s += sRed[g2 * STRIDE + o];
        out[n * 288 + w2_ * 9 + CGT<C>::KB + kk] += s * (1.f / 32.f);
    }
}

template<int C>
__device__ void path_uvu2(const float* __restrict__ x, const float* __restrict__ Wp,
                          float* __restrict__ out, float* __restrict__ sT, int tid) {
    constexpr int DK = CGT<C>::DK;
    stage1<C>(x, x, sT, tid);
    __syncthreads();
    for (int o = tid; o < NB * 32 * DK; o += 256) {
        int n = o / (32 * DK);
        int r = o - n * 32 * DK;
        int u = r / DK, kk = r - u * DK;
        const float* Wr = Wp + u * 32;
        const float* Tr = &sT[(n * DK + kk) * 1024 + u * 32];
        float s = 0.f;
#pragma unroll 8
        for (int v = 0; v < 32; v++) s += Tr[v] * __ldg(Wr + v);
        out[n * 288 + u * 9 + CGT<C>::KB + kk] += s * (1.f / SQM);
    }
    __syncthreads();
}

__device__ void lin_multi(const float* in, const float* __restrict__ W, float* out, bool accum, int tid) {
    for (int o = tid; o < NB * 288; o += 256) {
        int n = o / 288, idx = o - n * 288;
        int ww = idx / 9, slot = idx - ww * 9;
        int l = c_LSLOT[slot];
        const float* Wl = W + l * 1024 + ww;
        const float* ib = in + n * 288;
        float s = 0.f;
#pragma unroll 8
        for (int u = 0; u < 32; u++) s += ib[u * 9 + slot] * __ldg(Wl + u * 32);
        s *= (1.f / SQM);
        if (accum) out[o] += s; else out[o] = s;
    }
}

/* -------------------- per-node main kernel (NB=2) ------------------- */
__global__ __launch_bounds__(256) void mace_node(
    const float* __restrict__ nf, const float* __restrict__ lin_o1,
    const float* __restrict__ o2w, const float* __restrict__ o2u,
    const float* __restrict__ o3a, const float* __restrict__ o3b,
    const float* __restrict__ mixw, const float* __restrict__ combw,
    const float* __restrict__ selfw, float* __restrict__ out) {
    extern __shared__ float smem[];
    float* sa   = smem;                 /* NB*288 */
    float* sbuf = sa + NB * 288;
    float* st2  = sbuf + NB * 288;
    float* smix = st2 + NB * 288;
    float* smsg = smix + NB * 288;
    float* sT   = smsg + NB * 288;      /* NB*5*1024 */
    float* sRed = sT + NB * 5 * 1024;   /* 8*NB*32*5 */
    int z0 = blockIdx.x * NB, tid = threadIdx.x;

    for (int o = tid; o < NB * 288; o += 256) {
        int n = o / 288, idx = o - n * 288;
        int u = idx / 9, slot = idx - u * 9;
        float inv = 1.f / fmaxf(g_cnt[z0 + n], 1.f);
        sa[o] = g_asum[(z0 + n) * 288 + mergecol(u, slot)] * inv;
        smsg[o] = 0.f;
    }
    __syncthreads();
    /* order 0 */
    lin_multi(sa, lin_o1, sbuf, false, tid); __syncthreads();
    lin_multi(sbuf, mixw, smix, false, tid); __syncthreads();
    lin_multi(smix, combw, smsg, true, tid); __syncthreads();
    /* order 1 */
    for (int o = tid; o < NB * 288; o += 256) sbuf[o] = 0.f;
    __syncthreads();
    path_pair2<1>(sa, sa, o2w,          sbuf, sT, sRed, tid);
    path_pair2<2>(sa, sa, o2w + 32768,  sbuf, sT, sRed, tid);
    path_pair2<6>(sa, sa, o2w + 65536,  sbuf, sT, sRed, tid);
    __syncthreads();
    path_uvu2<0> (sa, o2u,        sbuf, sT, tid);
    path_uvu2<4> (sa, o2u + 1024, sbuf, sT, tid);
    path_uvu2<5> (sa, o2u + 2048, sbuf, sT, tid);
    path_uvu2<9> (sa, o2u + 3072, sbuf, sT, tid);
    path_uvu2<10>(sa, o2u + 4096, sbuf, sT, tid);
    lin_multi(sbuf, mixw + 3072, smix, false, tid); __syncthreads();
    lin_multi(smix, combw + 3072, smsg, true, tid); __syncthreads();
    /* order 2: b3 = pair(pair(a,a,o3a), a, o3b) */
    for (int o = tid; o < NB * 288; o += 256) st2[o] = 0.f;
    __syncthreads();
    path_pair2<0>(sa, sa, o3a,            st2, sT, sRed, tid);
    path_pair2<1>(sa, sa, o3a + 32768,    st2, sT, sRed, tid);
    path_pair2<2>(sa, sa, o3a + 65536,    st2, sT, sRed, tid);
    path_pair2<3>(sa, sa, o3a + 98304,    st2, sT, sRed, tid);
    path_pair2<4>(sa, sa, o3a + 131072,   st2, sT, sRed, tid);
    path_pair2<5>(sa, sa, o3a + 163840,   st2, sT, sRed, tid);
    path_pair2<6>(sa, sa, o3a + 196608,   st2, sT, sRed, tid);
    path_pair2<7>(sa, sa, o3a + 229376,   st2, sT, sRed, tid);
    path_pair2<8>(sa, sa, o3a + 262144,   st2, sT, sRed, tid);
    path_pair2<9>(sa, sa, o3a + 294912,   st2, sT, sRed, tid);
    path_pair2<10>(sa, sa, o3a + 327680,  st2, sT, sRed, tid);
    __syncthreads();
    for (int o = tid; o < NB * 288; o += 256) sbuf[o] = 0.f;
    __syncthreads();
    path_pair2<0>(st2, sa, o3b,           sbuf, sT, sRed, tid);
    path_pair2<1>(st2, sa, o3b + 32768,   sbuf, sT, sRed, tid);
    path_pair2<2>(st2, sa, o3b + 65536,   sbuf, sT, sRed, tid);
    path_pair2<3>(st2, sa, o3b + 98304,   sbuf, sT, sRed, tid);
    path_pair2<4>(st2, sa, o3b + 131072,  sbuf, sT, sRed, tid);
    path_pair2<5>(st2, sa, o3b + 163840,  sbuf, sT, sRed, tid);
    path_pair2<6>(st2, sa, o3b + 196608,  sbuf, sT, sRed, tid);
    path_pair2<7>(st2, sa, o3b + 229376,  sbuf, sT, sRed, tid);
    path_pair2<8>(st2, sa, o3b + 262144,  sbuf, sT, sRed, tid);
    path_pair2<9>(st2, sa, o3b + 294912,  sbuf, sT, sRed, tid);
    path_pair2<10>(st2, sa, o3b + 327680, sbuf, sT, sRed, tid);
    __syncthreads();
    lin_multi(sbuf, mixw + 6144, smix, false, tid); __syncthreads();
    lin_multi(smix, combw + 6144, smsg, true, tid); __syncthreads();
    /* self interaction */
    if (tid < NB * 32) {
        int n = tid >> 5, w = tid & 31;
        const float* r = nf + (z0 + n) * 32;
        float s = 0.f;
#pragma unroll 8
        for (int v = 0; v < 32; v++) s += r[v] * __ldg(selfw + v * 32 + w);
        smsg[n * 288 + w * 9] += s * (1.f / SQM);
    }
    __syncthreads();
    for (int o = tid; o < NB * 288; o += 256) {
        int n = o / 288, idx = o - n * 288;
        int u = idx / 9, slot = idx - u * 9;
        out[(z0 + n) * 288 + mergecol(u, slot)] = smsg[o];
    }
}

/* -------------------- launch ---------------------------------------- */
extern "C" void kernel_launch(void* const* d_in, const int* in_sizes, int n_in,
                              void* d_out, int out_size) {
    const float* nf    = (const float*)d_in[0];
    const int*   ei    = (const int*)d_in[1];
    const float* sh    = (const float*)d_in[2];
    const float* rad   = (const float*)d_in[3];
    const float* attr  = (const float*)d_in[4];
    const float* w1    = (const float*)d_in[5];
    const float* b1    = (const float*)d_in[6];
    const float* w2    = (const float*)d_in[7];
    const float* b2    = (const float*)d_in[8];
    const float* w3    = (const float*)d_in[9];
    const float* b3    = (const float*)d_in[10];
    const float* aw    = (const float*)d_in[11];
    const float* ab    = (const float*)d_in[12];
    const float* emb   = (const float*)d_in[13];
    const float* lino1 = (const float*)d_in[14];
    const float* o2w   = (const float*)d_in[15];
    const float* o2u   = (const float*)d_in[16];
    const float* o3a   = (const float*)d_in[17];
    const float* o3b   = (const float*)d_in[18];
    const float* mixw  = (const float*)d_in[19];
    const float* combw = (const float*)d_in[20];
    const float* selfw = (const float*)d_in[21];

    cudaFuncSetAttribute(mace_node, cudaFuncAttributeMaxDynamicSharedMemorySize, SMEM_NODE_BYTES);

    mace_init_A3<<<(2080 * 96 + 255) / 256, 256>>>(aw, ab);
    mace_zero<<<(N_NODES * 288 + 255) / 256, 256>>>();
    mace_h<<<N_NODES / 8, 256>>>(nf, emb);
    mace_mlp<<<N_EDGES / 8, 512>>>(ei, rad, attr, w1, b1, w2, b2, w3, b3);
    mace_edge_gemm<<<N_EDGES / 64, 256>>>(ei, sh);
    mace_node<<<N_NODES / NB, 256, SMEM_NODE_BYTES>>>(nf, lino1, o2w, o2u, o3a, o3b,
                                                      mixw, combw, selfw, (float*)d_out);
}

// round 6
// speedup vs baseline: 1.8486x; 1.0740x over previous
#include <cuda_runtime.h>
#include <math.h>

#define N_NODES 10000
#define N_EDGES 64000
#define RHID 64
#define SQM 5.656854249492381f
#define NB 2
#define SMEM_NODE_BYTES 62720

__device__ float g_h[N_NODES * 32];
__device__ float g_rf[N_EDGES * RHID];
__device__ float g_A3[2080 * 96];
__device__ float g_asum[N_NODES * 288];
__device__ float g_cnt[N_NODES];

/* ---------------- packed fp32x2 helpers (Blackwell FFMA2) ----------- */
typedef unsigned long long u64t;
__device__ __forceinline__ u64t pack2(float a, float b) {
    u64t r; asm("mov.b64 %0,{%1,%2};" : "=l"(r) : "f"(a), "f"(b)); return r;
}
__device__ __forceinline__ u64t pack1(float a) { return pack2(a, a); }
__device__ __forceinline__ void unpack2(u64t p, float& a, float& b) {
    asm("mov.b64 {%0,%1},%2;" : "=f"(a), "=f"(b) : "l"(p));
}
__device__ __forceinline__ void fma2(u64t& d, u64t a, u64t b) {
    asm("fma.rn.f32x2 %0,%1,%2,%0;" : "+l"(d) : "l"(a), "l"(b));
}
__device__ __forceinline__ u64t mul2(u64t a, u64t b) {
    u64t r; asm("mul.rn.f32x2 %0,%1,%2;" : "=l"(r) : "l"(a), "l"(b)); return r;
}

/* ----------------- hardcoded Clebsch-Gordan tables ------------------ */
#define R3f   0.57735026918962576f
#define R5f   0.44721359549995794f
#define R10f  0.31622776601683794f
#define R30f  0.18257418583505536f
#define R30x2 0.36514837167011072f
#define CNA   0.20701966780270626f
#define CNB   0.23904572186687872f
#define CNC   0.11952286093343936f

template<int N> struct IC { static constexpr int v = N; };
#define T3(i,j,k,val) f(IC<i>{}, IC<j>{}, IC<k>{}, val)

template<int C> struct CGT;
template<> struct CGT<0> { static constexpr int DK=1,IB=0,JB=0,KB=0;
  template<class F> __device__ static void terms(F f){ T3(0,0,0,1.f); } };
template<> struct CGT<1> { static constexpr int DK=3,IB=0,JB=1,KB=1;
  template<class F> __device__ static void terms(F f){
    T3(0,0,0,R3f); T3(0,1,1,R3f); T3(0,2,2,R3f); } };
template<> struct CGT<2> { static constexpr int DK=5,IB=0,JB=4,KB=4;
  template<class F> __device__ static void terms(F f){
    T3(0,0,0,R5f); T3(0,1,1,R5f); T3(0,2,2,R5f); T3(0,3,3,R5f); T3(0,4,4,R5f); } };
template<> struct CGT<3> { static constexpr int DK=3,IB=1,JB=0,KB=1;
  template<class F> __device__ static void terms(F f){
    T3(0,0,0,R3f); T3(1,0,1,R3f); T3(2,0,2,R3f); } };
template<> struct CGT<4> { static constexpr int DK=1,IB=1,JB=1,KB=0;
  template<class F> __device__ static void terms(F f){
    T3(0,0,0,R3f); T3(1,1,0,R3f); T3(2,2,0,R3f); } };
template<> struct CGT<5> { static constexpr int DK=5,IB=1,JB=1,KB=4;
  template<class F> __device__ static void terms(F f){
    T3(0,1,0,R10f); T3(1,0,0,R10f); T3(1,2,1,R10f); T3(2,1,1,R10f);
    T3(0,0,2,-R30f); T3(1,1,2,-R30f); T3(2,2,2,R30x2);
    T3(0,2,3,R10f); T3(2,0,3,R10f); T3(0,0,4,R10f); T3(1,1,4,-R10f); } };
template<> struct CGT<6> { static constexpr int DK=3,IB=1,JB=4,KB=1;
  template<class F> __device__ static void terms(F f){
    T3(0,0,1,R10f); T3(1,0,0,R10f); T3(1,1,2,R10f); T3(2,1,1,R10f);
    T3(0,2,0,-R30f); T3(1,2,1,-R30f); T3(2,2,2,R30x2);
    T3(0,3,2,R10f); T3(2,3,0,R10f); T3(0,4,0,R10f); T3(1,4,1,-R10f); } };
template<> struct CGT<7> { static constexpr int DK=5,IB=4,JB=0,KB=4;
  template<class F> __device__ static void terms(F f){
    T3(0,0,0,R5f); T3(1,0,1,R5f); T3(2,0,2,R5f); T3(3,0,3,R5f); T3(4,0,4,R5f); } };
template<> struct CGT<8> { static constexpr int DK=3,IB=4,JB=1,KB=1;
  template<class F> __device__ static void terms(F f){
    T3(0,0,1,R10f); T3(0,1,0,R10f); T3(1,1,2,R10f); T3(1,2,1,R10f);
    T3(2,0,0,-R30f); T3(2,1,1,-R30f); T3(2,2,2,R30x2);
    T3(3,0,2,R10f); T3(3,2,0,R10f); T3(4,0,0,R10f); T3(4,1,1,-R10f); } };
template<> struct CGT<9> { static constexpr int DK=1,IB=4,JB=4,KB=0;
  template<class F> __device__ static void terms(F f){
    T3(0,0,0,R5f); T3(1,1,0,R5f); T3(2,2,0,R5f); T3(3,3,0,R5f); T3(4,4,0,R5f); } };
template<> struct CGT<10> { static constexpr int DK=5,IB=4,JB=4,KB=4;
  template<class F> __device__ static void terms(F f){
    T3(0,1,3,CNA); T3(0,3,1,CNA); T3(1,0,3,CNA); T3(1,3,0,CNA); T3(3,0,1,CNA); T3(3,1,0,CNA);
    T3(0,0,2,-CNB); T3(0,2,0,-CNB); T3(2,0,0,-CNB);
    T3(1,1,2,CNC); T3(1,2,1,CNC); T3(2,1,1,CNC);
    T3(3,3,2,CNC); T3(3,2,3,CNC); T3(2,3,3,CNC);
    T3(1,1,4,-CNA); T3(1,4,1,-CNA); T3(4,1,1,-CNA);
    T3(3,3,4,CNA); T3(3,4,3,CNA); T3(4,3,3,CNA);
    T3(2,2,2,CNB);
    T3(2,4,4,-CNB); T3(4,2,4,-CNB); T3(4,4,2,-CNB); } };

__constant__ int c_LSLOT[9] = {0,1,1,1,2,2,2,2,2};

__device__ __forceinline__ int mergecol(int u, int slot) {
    if (slot == 0) return u;
    if (slot < 4)  return 32 + u * 3 + (slot - 1);
    return 128 + u * 5 + (slot - 4);
}

/* ---------------- fused init: zero + cnt + A3 repack ---------------- */
__global__ void mace_init(const float* __restrict__ aw, const float* __restrict__ ab) {
    int idx = blockIdx.x * blockDim.x + threadIdx.x;
    if (idx < N_NODES * 288) g_asum[idx] = 0.f;
    if (idx < N_NODES)       g_cnt[idx]  = 0.f;
    if (idx < 2080 * 96) {
        int k = idx / 96, n = idx - k * 96;
        int l = n >> 5, ww = n & 31;
        const float rsd[3] = {1.f, 0.57735026918962576f, 0.44721359549995794f};
        float scale = rsd[l] * (1.f / SQM);
        float v;
        if (k < 2048) { int r = k >> 5, u = k & 31; v = aw[r * 3072 + l * 1024 + u * 32 + ww]; }
        else          { int u = k - 2048;           v = ab[l * 1024 + u * 32 + ww]; }
        g_A3[idx] = v * scale;
    }
}

/* ------------- fused front: edge MLP blocks + node-h blocks --------- */
__global__ __launch_bounds__(512) void mace_front(
    const int* __restrict__ ei, const float* __restrict__ rad, const float* __restrict__ attr,
    const float* __restrict__ w1, const float* __restrict__ b1,
    const float* __restrict__ w2, const float* __restrict__ b2,
    const float* __restrict__ w3, const float* __restrict__ b3,
    const float* __restrict__ nf, const float* __restrict__ emb) {
    __shared__ float w1s[24 * 64], w2s[64 * 64], w3s[64 * 64];
    __shared__ float b1s[64], b2s[64], b3s[64];
    __shared__ float rin[8][24], x1[8][64], x2[8][64];
    int tid = threadIdx.x;
    if (blockIdx.x >= 8000) {                 /* ---- h branch ---- */
        int z = (blockIdx.x - 8000) * 16 + (tid >> 5);
        int ww = tid & 31;
        const float* r = nf + z * 32;
        float s = 0.f;
#pragma unroll 8
        for (int u = 0; u < 32; u++) s += r[u] * emb[u * 32 + ww];
        g_h[z * 32 + ww] = s * (1.f / SQM);
        return;
    }
    /* ---- mlp branch ---- */
    for (int i = tid; i < 1536; i += 512) w1s[i] = w1[i];
    for (int i = tid; i < 4096; i += 512) { w2s[i] = w2[i]; w3s[i] = w3[i]; }
    if (tid < 64) { b1s[tid] = b1[tid]; b2s[tid] = b2[tid]; b3s[tid] = b3[tid]; }
    int eg = tid >> 6, t = tid & 63;
    int e = blockIdx.x * 8 + eg;
    if (t < 8)       rin[eg][t] = rad[e * 8 + t];
    else if (t < 24) rin[eg][t] = attr[e * 16 + (t - 8)];
    __syncthreads();
    float s = b1s[t];
#pragma unroll
    for (int k = 0; k < 24; k++) s += rin[eg][k] * w1s[k * 64 + t];
    s = s / (1.f + expf(-s));
    x1[eg][t] = s;
    __syncthreads();
    s = b2s[t];
#pragma unroll 8
    for (int k = 0; k < 64; k++) s += x1[eg][k] * w2s[k * 64 + t];
    s = s / (1.f + expf(-s));
    x2[eg][t] = s;
    __syncthreads();
    s = b3s[t];
#pragma unroll 8
    for (int k = 0; k < 64; k++) s += x2[eg][k] * w3s[k * 64 + t];
    g_rf[e * 64 + t] = s;
    if (t == 0) atomicAdd(&g_cnt[ei[N_EDGES + e]], 1.f);
}

/* ------------ fused edge GEMM (f32x2) + SH expand + scatter --------- */
__global__ __launch_bounds__(256) void mace_edge_gemm(
    const int* __restrict__ ei, const float* __restrict__ sh) {
    __shared__ int s_src[64], s_dst[64];
    __shared__ float s_sh[64 * 9];
    __shared__ __align__(8) float Hs2[32 * 64];     /* [u][edge] */
    __shared__ float RFs[64 * 64];
    __shared__ float At[32 * 96];
    int tid = threadIdx.x;
    int e0 = blockIdx.x * 64;
    for (int i = tid; i < 64; i += 256) { s_src[i] = ei[e0 + i]; s_dst[i] = ei[N_EDGES + e0 + i]; }
    for (int i = tid; i < 576; i += 256) s_sh[i] = sh[e0 * 9 + i];
    __syncthreads();
    for (int i = tid; i < 2048; i += 256) { int u = i >> 6, e = i & 63; Hs2[u * 64 + e] = g_h[s_src[e] * 32 + u]; }
    for (int i = tid; i < 4096; i += 256) { int e = i >> 6, r = i & 63; RFs[e * 64 + r] = g_rf[(e0 + e) * 64 + r]; }
    int tx = tid & 31, ty = tid >> 5;
    u64t acc2[4][3];
#pragma unroll
    for (int p = 0; p < 4; p++) { acc2[p][0] = pack2(0.f,0.f); acc2[p][1] = pack2(0.f,0.f); acc2[p][2] = pack2(0.f,0.f); }

    for (int kc = 0; kc < 2080; kc += 32) {
        __syncthreads();
        for (int i = tid; i < 3072; i += 256) {
            int kk = i / 96, n = i - kk * 96;
            At[i] = g_A3[(kc + kk) * 96 + n];
        }
        __syncthreads();
        bool bias = (kc >= 2048);
        int r = kc >> 5;
        u64t prf[4];
#pragma unroll
        for (int p = 0; p < 4; p++) {
            int e = ty * 8 + 2 * p;
            prf[p] = bias ? pack2(1.f, 1.f) : pack2(RFs[e * 64 + r], RFs[(e + 1) * 64 + r]);
        }
#pragma unroll 4
        for (int kk = 0; kk < 32; kk++) {
            u64t pa0 = pack1(At[kk * 96 + tx]);
            u64t pa1 = pack1(At[kk * 96 + 32 + tx]);
            u64t pa2 = pack1(At[kk * 96 + 64 + tx]);
            const u64t* hrow = (const u64t*)&Hs2[kk * 64 + ty * 8];
#pragma unroll
            for (int p = 0; p < 4; p++) {
                u64t pp = mul2(prf[p], hrow[p]);
                fma2(acc2[p][0], pp, pa0);
                fma2(acc2[p][1], pp, pa1);
                fma2(acc2[p][2], pp, pa2);
            }
        }
    }
    __syncthreads();
    float m[8][3];
#pragma unroll
    for (int p = 0; p < 4; p++)
#pragma unroll
        for (int c = 0; c < 3; c++) unpack2(acc2[p][c], m[2 * p][c], m[2 * p + 1][c]);
#pragma unroll
    for (int i = 0; i < 8; i++) {
        int e = ty * 8 + i;
        float* ob = &g_asum[s_dst[e] * 288];
        const float* shv = &s_sh[e * 9];
        atomicAdd(ob + tx, m[i][0] * shv[0]);
#pragma unroll
        for (int q = 0; q < 3; q++) atomicAdd(ob + 32 + tx * 3 + q, m[i][1] * shv[1 + q]);
#pragma unroll
        for (int q = 0; q < 5; q++) atomicAdd(ob + 128 + tx * 5 + q, m[i][2] * shv[4 + q]);
    }
}

/* -------------------- per-node CG machinery (NB=2) ------------------ */
template<int C>
__device__ __forceinline__ void stage1(const float* __restrict__ x, const float* __restrict__ y,
                                       float* __restrict__ sT, int tid) {
    constexpr int DK = CGT<C>::DK;
#pragma unroll
    for (int rep = 0; rep < NB * 4; rep++) {
        int idx = rep * 256 + tid;
        int n = idx >> 10, uv = idx & 1023;
        int u = uv >> 5, v = uv & 31;
        const float* xr = x + n * 288 + u * 9 + CGT<C>::IB;
        const float* yr = y + n * 288 + v * 9 + CGT<C>::JB;
        float acc[DK];
#pragma unroll
        for (int kk = 0; kk < DK; kk++) acc[kk] = 0.f;
        CGT<C>::terms([&](auto ti, auto tj, auto tk, float val) {
            acc[tk.v] = fmaf(xr[ti.v] * yr[tj.v], val, acc[tk.v]);
        });
#pragma unroll
        for (int kk = 0; kk < DK; kk++) sT[(n * DK + kk) * 1024 + uv] = acc[kk];
    }
}

template<int C>
__device__ void path_pair2(const float* __restrict__ x, const float* __restrict__ y,
                           const float* __restrict__ Wp, float* __restrict__ out,
                           float* __restrict__ sT, float* __restrict__ sRed, int tid) {
    constexpr int DK = CGT<C>::DK;
    constexpr int STRIDE = NB * 32 * DK;
    stage1<C>(x, y, sT, tid);
    __syncthreads();
    int g = tid >> 5, w = tid & 31;
    u64t part[NB][DK];
#pragma unroll
    for (int n = 0; n < NB; n++)
#pragma unroll
        for (int kk = 0; kk < DK; kk++) part[n][kk] = pack2(0.f, 0.f);
    const float* Wg = Wp + g * 128 * 32 + w;
#pragma unroll 2
    for (int q = 0; q < 128; q += 4) {
        float w0 = __ldg(Wg + q * 32),       w1 = __ldg(Wg + q * 32 + 32);
        float w2 = __ldg(Wg + q * 32 + 64),  w3 = __ldg(Wg + q * 32 + 96);
        u64t pwA = pack2(w0, w1), pwB = pack2(w2, w3);
        int base = g * 128 + q;
#pragma unroll
        for (int n = 0; n < NB; n++)
#pragma unroll
            for (int kk = 0; kk < DK; kk++) {
                longlong2 tv = *(const longlong2*)&sT[(n * DK + kk) * 1024 + base];
                fma2(part[n][kk], (u64t)tv.x, pwA);
                fma2(part[n][kk], (u64t)tv.y, pwB);
            }
    }
#pragma unroll
    for (int n = 0; n < NB; n++)
#pragma unroll
        for (int kk = 0; kk < DK; kk++) {
            float lo, hi;
            unpack2(part[n][kk], lo, hi);
            sRed[g * STRIDE + (n * 32 + w) * DK + kk] = lo + hi;
        }
    __syncthreads();
    for (int o = tid; o < STRIDE; o += 256) {
        int kk = o % DK, nw = o / DK;
        int n = nw >> 5, w2_ = nw & 31;
        float s = 0.f;
#pragma unroll
        for (int g2 = 0; g2 < 8; g2++) s += sRed[g2 * STRIDE + o];
        out[n * 288 + w2_ * 9 + CGT<C>::KB + kk] += s * (1.f / 32.f);
    }
}

template<int C>
__device__ void path_uvu2(const float* __restrict__ x, const float* __restrict__ Wp,
                          float* __restrict__ out, float* __restrict__ sT, int tid) {
    constexpr int DK = CGT<C>::DK;
    stage1<C>(x, x, sT, tid);
    __syncthreads();
    for (int o = tid; o < NB * 32 * DK; o += 256) {
        int n = o / (32 * DK);
        int r = o - n * 32 * DK;
        int u = r / DK, kk = r - u * DK;
        const float* Wr = Wp + u * 32;
        const float* Tr = &sT[(n * DK + kk) * 1024 + u * 32];
        float s = 0.f;
#pragma unroll 8
        for (int v = 0; v < 32; v++) s += Tr[v] * __ldg(Wr + v);
        out[n * 288 + u * 9 + CGT<C>::KB + kk] += s * (1.f / SQM);
    }
    __syncthreads();
}

__device__ void lin_multi(const float* in, const float* __restrict__ W, float* out, bool accum, int tid) {
    for (int o = tid; o < NB * 288; o += 256) {
        int n = o / 288, idx = o - n * 288;
        int ww = idx / 9, slot = idx - ww * 9;
        int l = c_LSLOT[slot];
        const float* Wl = W + l * 1024 + ww;
        const float* ib = in + n * 288;
        float s = 0.f;
#pragma unroll 8
        for (int u = 0; u < 32; u++) s += ib[u * 9 + slot] * __ldg(Wl + u * 32);
        s *= (1.f / SQM);
        if (accum) out[o] += s; else out[o] = s;
    }
}

/* -------------------- per-node main kernel (NB=2) ------------------- */
__global__ __launch_bounds__(256) void mace_node(
    const float* __restrict__ nf, const float* __restrict__ lin_o1,
    const float* __restrict__ o2w, const float* __restrict__ o2u,
    const float* __restrict__ o3a, const float* __restrict__ o3b,
    const float* __restrict__ mixw, const float* __restrict__ combw,
    const float* __restrict__ selfw, float* __restrict__ out) {
    extern __shared__ float smem[];
    float* sa   = smem;
    float* sbuf = sa + NB * 288;
    float* st2  = sbuf + NB * 288;
    float* smix = st2 + NB * 288;
    float* smsg = smix + NB * 288;
    float* sT   = smsg + NB * 288;
    float* sRed = sT + NB * 5 * 1024;
    int z0 = blockIdx.x * NB, tid = threadIdx.x;

    for (int o = tid; o < NB * 288; o += 256) {
        int n = o / 288, idx = o - n * 288;
        int u = idx / 9, slot = idx - u * 9;
        float inv = 1.f / fmaxf(g_cnt[z0 + n], 1.f);
        sa[o] = g_asum[(z0 + n) * 288 + mergecol(u, slot)] * inv;
        smsg[o] = 0.f;
    }
    __syncthreads();
    lin_multi(sa, lin_o1, sbuf, false, tid); __syncthreads();
    lin_multi(sbuf, mixw, smix, false, tid); __syncthreads();
    lin_multi(smix, combw, smsg, true, tid); __syncthreads();
    for (int o = tid; o < NB * 288; o += 256) sbuf[o] = 0.f;
    __syncthreads();
    path_pair2<1>(sa, sa, o2w,          sbuf, sT, sRed, tid);
    path_pair2<2>(sa, sa, o2w + 32768,  sbuf, sT, sRed, tid);
    path_pair2<6>(sa, sa, o2w + 65536,  sbuf, sT, sRed, tid);
    __syncthreads();
    path_uvu2<0> (sa, o2u,        sbuf, sT, tid);
    path_uvu2<4> (sa, o2u + 1024, sbuf, sT, tid);
    path_uvu2<5> (sa, o2u + 2048, sbuf, sT, tid);
    path_uvu2<9> (sa, o2u + 3072, sbuf, sT, tid);
    path_uvu2<10>(sa, o2u + 4096, sbuf, sT, tid);
    lin_multi(sbuf, mixw + 3072, smix, false, tid); __syncthreads();
    lin_multi(smix, combw + 3072, smsg, true, tid); __syncthreads();
    for (int o = tid; o < NB * 288; o += 256) st2[o] = 0.f;
    __syncthreads();
    path_pair2<0>(sa, sa, o3a,            st2, sT, sRed, tid);
    path_pair2<1>(sa, sa, o3a + 32768,    st2, sT, sRed, tid);
    path_pair2<2>(sa, sa, o3a + 65536,    st2, sT, sRed, tid);
    path_pair2<3>(sa, sa, o3a + 98304,    st2, sT, sRed, tid);
    path_pair2<4>(sa, sa, o3a + 131072,   st2, sT, sRed, tid);
    path_pair2<5>(sa, sa, o3a + 163840,   st2, sT, sRed, tid);
    path_pair2<6>(sa, sa, o3a + 196608,   st2, sT, sRed, tid);
    path_pair2<7>(sa, sa, o3a + 229376,   st2, sT, sRed, tid);
    path_pair2<8>(sa, sa, o3a + 262144,   st2, sT, sRed, tid);
    path_pair2<9>(sa, sa, o3a + 294912,   st2, sT, sRed, tid);
    path_pair2<10>(sa, sa, o3a + 327680,  st2, sT, sRed, tid);
    __syncthreads();
    for (int o = tid; o < NB * 288; o += 256) sbuf[o] = 0.f;
    __syncthreads();
    path_pair2<0>(st2, sa, o3b,           sbuf, sT, sRed, tid);
    path_pair2<1>(st2, sa, o3b + 32768,   sbuf, sT, sRed, tid);
    path_pair2<2>(st2, sa, o3b + 65536,   sbuf, sT, sRed, tid);
    path_pair2<3>(st2, sa, o3b + 98304,   sbuf, sT, sRed, tid);
    path_pair2<4>(st2, sa, o3b + 131072,  sbuf, sT, sRed, tid);
    path_pair2<5>(st2, sa, o3b + 163840,  sbuf, sT, sRed, tid);
    path_pair2<6>(st2, sa, o3b + 196608,  sbuf, sT, sRed, tid);
    path_pair2<7>(st2, sa, o3b + 229376,  sbuf, sT, sRed, tid);
    path_pair2<8>(st2, sa, o3b + 262144,  sbuf, sT, sRed, tid);
    path_pair2<9>(st2, sa, o3b + 294912,  sbuf, sT, sRed, tid);
    path_pair2<10>(st2, sa, o3b + 327680, sbuf, sT, sRed, tid);
    __syncthreads();
    lin_multi(sbuf, mixw + 6144, smix, false, tid); __syncthreads();
    lin_multi(smix, combw + 6144, smsg, true, tid); __syncthreads();
    if (tid < NB * 32) {
        int n = tid >> 5, w = tid & 31;
        const float* r = nf + (z0 + n) * 32;
        float s = 0.f;
#pragma unroll 8
        for (int v = 0; v < 32; v++) s += r[v] * __ldg(selfw + v * 32 + w);
        smsg[n * 288 + w * 9] += s * (1.f / SQM);
    }
    __syncthreads();
    for (int o = tid; o < NB * 288; o += 256) {
        int n = o / 288, idx = o - n * 288;
        int u = idx / 9, slot = idx - u * 9;
        out[(z0 + n) * 288 + mergecol(u, slot)] = smsg[o];
    }
}

/* -------------------- launch ---------------------------------------- */
extern "C" void kernel_launch(void* const* d_in, const int* in_sizes, int n_in,
                              void* d_out, int out_size) {
    const float* nf    = (const float*)d_in[0];
    const int*   ei    = (const int*)d_in[1];
    const float* sh    = (const float*)d_in[2];
    const float* rad   = (const float*)d_in[3];
    const float* attr  = (const float*)d_in[4];
    const float* w1    = (const float*)d_in[5];
    const float* b1    = (const float*)d_in[6];
    const float* w2    = (const float*)d_in[7];
    const float* b2    = (const float*)d_in[8];
    const float* w3    = (const float*)d_in[9];
    const float* b3    = (const float*)d_in[10];
    const float* aw    = (const float*)d_in[11];
    const float* ab    = (const float*)d_in[12];
    const float* emb   = (const float*)d_in[13];
    const float* lino1 = (const float*)d_in[14];
    const float* o2w   = (const float*)d_in[15];
    const float* o2u   = (const float*)d_in[16];
    const float* o3a   = (const float*)d_in[17];
    const float* o3b   = (const float*)d_in[18];
    const float* mixw  = (const float*)d_in[19];
    const float* combw = (const float*)d_in[20];
    const float* selfw = (const float*)d_in[21];

    cudaFuncSetAttribute(mace_node, cudaFuncAttributeMaxDynamicSharedMemorySize, SMEM_NODE_BYTES);

    mace_init<<<(N_NODES * 288 + 255) / 256, 256>>>(aw, ab);
    mace_front<<<8000 + 625, 512>>>(ei, rad, attr, w1, b1, w2, b2, w3, b3, nf, emb);
    mace_edge_gemm<<<N_EDGES / 64, 256>>>(ei, sh);
    mace_node<<<N_NODES / NB, 256, SMEM_NODE_BYTES>>>(nf, lino1, o2w, o2u, o3a, o3b,
                                                      mixw, combw, selfw, (float*)d_out);
}

// round 7
// speedup vs baseline: 2.0600x; 1.1143x over previous
#include <cuda_runtime.h>
#include <math.h>

#define N_NODES 10000
#define N_EDGES 64000
#define RHID 64
#define SQM 5.656854249492381f
#define NB 2
#define SMEM_NODE_BYTES 52480

__device__ float g_h[N_NODES * 32];
__device__ float g_rf[N_EDGES * RHID];
__device__ float g_A3[2080 * 96];
__device__ float g_asum[N_NODES * 288];
__device__ float g_cnt[N_NODES];

/* ---------------- packed fp32x2 helpers (Blackwell FFMA2) ----------- */
typedef unsigned long long u64t;
__device__ __forceinline__ u64t pack2(float a, float b) {
    u64t r; asm("mov.b64 %0,{%1,%2};" : "=l"(r) : "f"(a), "f"(b)); return r;
}
__device__ __forceinline__ u64t pack1(float a) { return pack2(a, a); }
__device__ __forceinline__ void unpack2(u64t p, float& a, float& b) {
    asm("mov.b64 {%0,%1},%2;" : "=f"(a), "=f"(b) : "l"(p));
}
__device__ __forceinline__ void fma2(u64t& d, u64t a, u64t b) {
    asm("fma.rn.f32x2 %0,%1,%2,%0;" : "+l"(d) : "l"(a), "l"(b));
}
__device__ __forceinline__ u64t mul2(u64t a, u64t b) {
    u64t r; asm("mul.rn.f32x2 %0,%1,%2;" : "=l"(r) : "l"(a), "l"(b)); return r;
}

/* ----------------- hardcoded Clebsch-Gordan tables ------------------ */
#define R3f   0.57735026918962576f
#define R5f   0.44721359549995794f
#define R10f  0.31622776601683794f
#define R30f  0.18257418583505536f
#define R30x2 0.36514837167011072f
#define CNA   0.20701966780270626f
#define CNB   0.23904572186687872f
#define CNC   0.11952286093343936f

template<int N> struct IC { static constexpr int v = N; };
#define T3(i,j,k,val) f(IC<i>{}, IC<j>{}, IC<k>{}, val)

template<int C> struct CGT;
template<> struct CGT<0> { static constexpr int DK=1,IB=0,JB=0,KB=0;
  template<class F> __device__ static void terms(F f){ T3(0,0,0,1.f); } };
template<> struct CGT<1> { static constexpr int DK=3,IB=0,JB=1,KB=1;
  template<class F> __device__ static void terms(F f){
    T3(0,0,0,R3f); T3(0,1,1,R3f); T3(0,2,2,R3f); } };
template<> struct CGT<2> { static constexpr int DK=5,IB=0,JB=4,KB=4;
  template<class F> __device__ static void terms(F f){
    T3(0,0,0,R5f); T3(0,1,1,R5f); T3(0,2,2,R5f); T3(0,3,3,R5f); T3(0,4,4,R5f); } };
template<> struct CGT<3> { static constexpr int DK=3,IB=1,JB=0,KB=1;
  template<class F> __device__ static void terms(F f){
    T3(0,0,0,R3f); T3(1,0,1,R3f); T3(2,0,2,R3f); } };
template<> struct CGT<4> { static constexpr int DK=1,IB=1,JB=1,KB=0;
  template<class F> __device__ static void terms(F f){
    T3(0,0,0,R3f); T3(1,1,0,R3f); T3(2,2,0,R3f); } };
template<> struct CGT<5> { static constexpr int DK=5,IB=1,JB=1,KB=4;
  template<class F> __device__ static void terms(F f){
    T3(0,1,0,R10f); T3(1,0,0,R10f); T3(1,2,1,R10f); T3(2,1,1,R10f);
    T3(0,0,2,-R30f); T3(1,1,2,-R30f); T3(2,2,2,R30x2);
    T3(0,2,3,R10f); T3(2,0,3,R10f); T3(0,0,4,R10f); T3(1,1,4,-R10f); } };
template<> struct CGT<6> { static constexpr int DK=3,IB=1,JB=4,KB=1;
  template<class F> __device__ static void terms(F f){
    T3(0,0,1,R10f); T3(1,0,0,R10f); T3(1,1,2,R10f); T3(2,1,1,R10f);
    T3(0,2,0,-R30f); T3(1,2,1,-R30f); T3(2,2,2,R30x2);
    T3(0,3,2,R10f); T3(2,3,0,R10f); T3(0,4,0,R10f); T3(1,4,1,-R10f); } };
template<> struct CGT<7> { static constexpr int DK=5,IB=4,JB=0,KB=4;
  template<class F> __device__ static void terms(F f){
    T3(0,0,0,R5f); T3(1,0,1,R5f); T3(2,0,2,R5f); T3(3,0,3,R5f); T3(4,0,4,R5f); } };
template<> struct CGT<8> { static constexpr int DK=3,IB=4,JB=1,KB=1;
  template<class F> __device__ static void terms(F f){
    T3(0,0,1,R10f); T3(0,1,0,R10f); T3(1,1,2,R10f); T3(1,2,1,R10f);
    T3(2,0,0,-R30f); T3(2,1,1,-R30f); T3(2,2,2,R30x2);
    T3(3,0,2,R10f); T3(3,2,0,R10f); T3(4,0,0,R10f); T3(4,1,1,-R10f); } };
template<> struct CGT<9> { static constexpr int DK=1,IB=4,JB=4,KB=0;
  template<class F> __device__ static void terms(F f){
    T3(0,0,0,R5f); T3(1,1,0,R5f); T3(2,2,0,R5f); T3(3,3,0,R5f); T3(4,4,0,R5f); } };
template<> struct CGT<10> { static constexpr int DK=5,IB=4,JB=4,KB=4;
  template<class F> __device__ static void terms(F f){
    T3(0,1,3,CNA); T3(0,3,1,CNA); T3(1,0,3,CNA); T3(1,3,0,CNA); T3(3,0,1,CNA); T3(3,1,0,CNA);
    T3(0,0,2,-CNB); T3(0,2,0,-CNB); T3(2,0,0,-CNB);
    T3(1,1,2,CNC); T3(1,2,1,CNC); T3(2,1,1,CNC);
    T3(3,3,2,CNC); T3(3,2,3,CNC); T3(2,3,3,CNC);
    T3(1,1,4,-CNA); T3(1,4,1,-CNA); T3(4,1,1,-CNA);
    T3(3,3,4,CNA); T3(3,4,3,CNA); T3(4,3,3,CNA);
    T3(2,2,2,CNB);
    T3(2,4,4,-CNB); T3(4,2,4,-CNB); T3(4,4,2,-CNB); } };

__device__ __forceinline__ int mergecol(int u, int slot) {
    if (slot == 0) return u;
    if (slot < 4)  return 32 + u * 3 + (slot - 1);
    return 128 + u * 5 + (slot - 4);
}

/* ---------------- fused init: zero + cnt + A3 repack ---------------- */
__global__ void mace_init(const float* __restrict__ aw, const float* __restrict__ ab) {
    int idx = blockIdx.x * blockDim.x + threadIdx.x;
    if (idx < N_NODES * 288) g_asum[idx] = 0.f;
    if (idx < N_NODES)       g_cnt[idx]  = 0.f;
    if (idx < 2080 * 96) {
        int k = idx / 96, n = idx - k * 96;
        int l = n >> 5, ww = n & 31;
        const float rsd[3] = {1.f, 0.57735026918962576f, 0.44721359549995794f};
        float scale = rsd[l] * (1.f / SQM);
        float v;
        if (k < 2048) { int r = k >> 5, u = k & 31; v = aw[r * 3072 + l * 1024 + u * 32 + ww]; }
        else          { int u = k - 2048;           v = ab[l * 1024 + u * 32 + ww]; }
        g_A3[idx] = v * scale;
    }
}

/* ------------- fused front: edge MLP blocks + node-h blocks --------- */
__global__ __launch_bounds__(512) void mace_front(
    const int* __restrict__ ei, const float* __restrict__ rad, const float* __restrict__ attr,
    const float* __restrict__ w1, const float* __restrict__ b1,
    const float* __restrict__ w2, const float* __restrict__ b2,
    const float* __restrict__ w3, const float* __restrict__ b3,
    const float* __restrict__ nf, const float* __restrict__ emb) {
    __shared__ float w1s[24 * 64], w2s[64 * 64], w3s[64 * 64];
    __shared__ float b1s[64], b2s[64], b3s[64];
    __shared__ float rin[8][24], x1[8][64], x2[8][64];
    int tid = threadIdx.x;
    if (blockIdx.x >= 8000) {
        int z = (blockIdx.x - 8000) * 16 + (tid >> 5);
        int ww = tid & 31;
        const float* r = nf + z * 32;
        float s = 0.f;
#pragma unroll 8
        for (int u = 0; u < 32; u++) s += r[u] * emb[u * 32 + ww];
        g_h[z * 32 + ww] = s * (1.f / SQM);
        return;
    }
    for (int i = tid; i < 1536; i += 512) w1s[i] = w1[i];
    for (int i = tid; i < 4096; i += 512) { w2s[i] = w2[i]; w3s[i] = w3[i]; }
    if (tid < 64) { b1s[tid] = b1[tid]; b2s[tid] = b2[tid]; b3s[tid] = b3[tid]; }
    int eg = tid >> 6, t = tid & 63;
    int e = blockIdx.x * 8 + eg;
    if (t < 8)       rin[eg][t] = rad[e * 8 + t];
    else if (t < 24) rin[eg][t] = attr[e * 16 + (t - 8)];
    __syncthreads();
    float s = b1s[t];
#pragma unroll
    for (int k = 0; k < 24; k++) s += rin[eg][k] * w1s[k * 64 + t];
    s = s / (1.f + expf(-s));
    x1[eg][t] = s;
    __syncthreads();
    s = b2s[t];
#pragma unroll 8
    for (int k = 0; k < 64; k++) s += x1[eg][k] * w2s[k * 64 + t];
    s = s / (1.f + expf(-s));
    x2[eg][t] = s;
    __syncthreads();
    s = b3s[t];
#pragma unroll 8
    for (int k = 0; k < 64; k++) s += x2[eg][k] * w3s[k * 64 + t];
    g_rf[e * 64 + t] = s;
    if (t == 0) atomicAdd(&g_cnt[ei[N_EDGES + e]], 1.f);
}

/* ------------ fused edge GEMM (f32x2) + SH expand + scatter --------- */
__global__ __launch_bounds__(256) void mace_edge_gemm(
    const int* __restrict__ ei, const float* __restrict__ sh) {
    __shared__ int s_src[64], s_dst[64];
    __shared__ float s_sh[64 * 9];
    __shared__ __align__(8) float Hs2[32 * 64];
    __shared__ float RFs[64 * 64];
    __shared__ float At[32 * 96];
    int tid = threadIdx.x;
    int e0 = blockIdx.x * 64;
    for (int i = tid; i < 64; i += 256) { s_src[i] = ei[e0 + i]; s_dst[i] = ei[N_EDGES + e0 + i]; }
    for (int i = tid; i < 576; i += 256) s_sh[i] = sh[e0 * 9 + i];
    __syncthreads();
    for (int i = tid; i < 2048; i += 256) { int u = i >> 6, e = i & 63; Hs2[u * 64 + e] = g_h[s_src[e] * 32 + u]; }
    for (int i = tid; i < 4096; i += 256) { int e = i >> 6, r = i & 63; RFs[e * 64 + r] = g_rf[(e0 + e) * 64 + r]; }
    int tx = tid & 31, ty = tid >> 5;
    u64t acc2[4][3];
#pragma unroll
    for (int p = 0; p < 4; p++) { acc2[p][0] = pack2(0.f,0.f); acc2[p][1] = pack2(0.f,0.f); acc2[p][2] = pack2(0.f,0.f); }

    for (int kc = 0; kc < 2080; kc += 32) {
        __syncthreads();
        for (int i = tid; i < 3072; i += 256) {
            int kk = i / 96, n = i - kk * 96;
            At[i] = g_A3[(kc + kk) * 96 + n];
        }
        __syncthreads();
        bool bias = (kc >= 2048);
        int r = kc >> 5;
        u64t prf[4];
#pragma unroll
        for (int p = 0; p < 4; p++) {
            int e = ty * 8 + 2 * p;
            prf[p] = bias ? pack2(1.f, 1.f) : pack2(RFs[e * 64 + r], RFs[(e + 1) * 64 + r]);
        }
#pragma unroll 4
        for (int kk = 0; kk < 32; kk++) {
            u64t pa0 = pack1(At[kk * 96 + tx]);
            u64t pa1 = pack1(At[kk * 96 + 32 + tx]);
            u64t pa2 = pack1(At[kk * 96 + 64 + tx]);
            const u64t* hrow = (const u64t*)&Hs2[kk * 64 + ty * 8];
#pragma unroll
            for (int p = 0; p < 4; p++) {
                u64t pp = mul2(prf[p], hrow[p]);
                fma2(acc2[p][0], pp, pa0);
                fma2(acc2[p][1], pp, pa1);
                fma2(acc2[p][2], pp, pa2);
            }
        }
    }
    __syncthreads();
    float m[8][3];
#pragma unroll
    for (int p = 0; p < 4; p++)
#pragma unroll
        for (int c = 0; c < 3; c++) unpack2(acc2[p][c], m[2 * p][c], m[2 * p + 1][c]);
#pragma unroll
    for (int i = 0; i < 8; i++) {
        int e = ty * 8 + i;
        float* ob = &g_asum[s_dst[e] * 288];
        const float* shv = &s_sh[e * 9];
        atomicAdd(ob + tx, m[i][0] * shv[0]);
#pragma unroll
        for (int q = 0; q < 3; q++) atomicAdd(ob + 32 + tx * 3 + q, m[i][1] * shv[1 + q]);
#pragma unroll
        for (int q = 0; q < 5; q++) atomicAdd(ob + 128 + tx * 5 + q, m[i][2] * shv[4 + q]);
    }
}

/* ----------- per-node CG machinery (NB=2, slot-major layout) -------- */
/* all node vectors: [n][slot*32 + u], slot-major rows of 32            */
template<int C>
__device__ __forceinline__ void stage1(const float* __restrict__ x, const float* __restrict__ y,
                                       float* __restrict__ sT, int tid) {
    constexpr int DK = CGT<C>::DK;
#pragma unroll
    for (int rep = 0; rep < NB * 2; rep++) {     /* NB*512 v-pairs / 256 */
        int idx = rep * 256 + tid;
        int n = idx >> 9, r = idx & 511;
        int u = r >> 4, v0 = (r & 15) * 2;
        const float* xr = x + n * 288 + CGT<C>::IB * 32 + u;
        const float* yr = y + n * 288 + CGT<C>::JB * 32 + v0;
        u64t acc[DK];
#pragma unroll
        for (int kk = 0; kk < DK; kk++) acc[kk] = pack2(0.f, 0.f);
        CGT<C>::terms([&](auto ti, auto tj, auto tk, float val) {
            u64t px = pack1(xr[ti.v * 32] * val);
            u64t py = *(const u64t*)&yr[tj.v * 32];
            fma2(acc[tk.v], px, py);
        });
#pragma unroll
        for (int kk = 0; kk < DK; kk++)
            *(u64t*)&sT[(n * DK + kk) * 1024 + u * 32 + v0] = acc[kk];
    }
}

template<int C>
__device__ void path_pair2(const float* __restrict__ x, const float* __restrict__ y,
                           const float* __restrict__ Wp, float* __restrict__ out,
                           float* __restrict__ sT, int tid) {
    constexpr int DK = CGT<C>::DK;
    stage1<C>(x, y, sT, tid);
    __syncthreads();
    int g = tid >> 5, w = tid & 31;
    u64t part[NB][DK];
#pragma unroll
    for (int n = 0; n < NB; n++)
#pragma unroll
        for (int kk = 0; kk < DK; kk++) part[n][kk] = pack2(0.f, 0.f);
    const float* Wg = Wp + g * 128 * 32 + w;
#pragma unroll 2
    for (int q = 0; q < 128; q += 4) {
        float w0 = __ldg(Wg + q * 32),       w1 = __ldg(Wg + q * 32 + 32);
        float w2 = __ldg(Wg + q * 32 + 64),  w3 = __ldg(Wg + q * 32 + 96);
        u64t pwA = pack2(w0, w1), pwB = pack2(w2, w3);
        int base = g * 128 + q;
#pragma unroll
        for (int n = 0; n < NB; n++)
#pragma unroll
            for (int kk = 0; kk < DK; kk++) {
                longlong2 tv = *(const longlong2*)&sT[(n * DK + kk) * 1024 + base];
                fma2(part[n][kk], (u64t)tv.x, pwA);
                fma2(part[n][kk], (u64t)tv.y, pwB);
            }
    }
#pragma unroll
    for (int n = 0; n < NB; n++)
#pragma unroll
        for (int kk = 0; kk < DK; kk++) {
            float lo, hi;
            unpack2(part[n][kk], lo, hi);
            atomicAdd(&out[n * 288 + (CGT<C>::KB + kk) * 32 + w], (lo + hi) * (1.f / 32.f));
        }
    __syncthreads();
}

template<int C>
__device__ void path_uvu2(const float* __restrict__ x, const float* __restrict__ Wp,
                          float* __restrict__ out, float* __restrict__ sT, int tid) {
    constexpr int DK = CGT<C>::DK;
    stage1<C>(x, x, sT, tid);
    __syncthreads();
    for (int o = tid; o < NB * 32 * DK; o += 256) {
        int n = o / (32 * DK);
        int r = o - n * 32 * DK;
        int u = r / DK, kk = r - u * DK;
        const u64t* Tp = (const u64t*)&sT[(n * DK + kk) * 1024 + u * 32];
        const float* Wr = Wp + u * 32;
        u64t accp = pack2(0.f, 0.f);
#pragma unroll 8
        for (int v2 = 0; v2 < 16; v2++) {
            u64t wv = *(const u64t*)&Wr[v2 * 2];
            fma2(accp, Tp[v2], wv);
        }
        float lo, hi; unpack2(accp, lo, hi);
        out[n * 288 + (CGT<C>::KB + kk) * 32 + u] += (lo + hi) * (1.f / SQM);
    }
    __syncthreads();
}

__device__ void lin_multi(const float* in, const float* __restrict__ W, float* out, bool accum, int tid) {
    for (int o = tid; o < NB * 288; o += 256) {
        int n = o / 288, idx = o - n * 288;
        int slot = idx >> 5, ww = idx & 31;
        int l = (slot == 0) ? 0 : (slot < 4 ? 1 : 2);
        const float* Wl = W + l * 1024 + ww;
        const float* ib = in + n * 288 + slot * 32;
        float s = 0.f;
#pragma unroll 8
        for (int u = 0; u < 32; u++) s += ib[u] * __ldg(Wl + u * 32);
        s *= (1.f / SQM);
        if (accum) out[o] += s; else out[o] = s;
    }
}

/* -------------------- per-node main kernel (NB=2) ------------------- */
__global__ __launch_bounds__(256, 4) void mace_node(
    const float* __restrict__ nf, const float* __restrict__ lin_o1,
    const float* __restrict__ o2w, const float* __restrict__ o2u,
    const float* __restrict__ o3a, const float* __restrict__ o3b,
    const float* __restrict__ mixw, const float* __restrict__ combw,
    const float* __restrict__ selfw, float* __restrict__ out) {
    extern __shared__ float smem[];
    float* sa   = smem;
    float* sbuf = sa + NB * 288;
    float* st2  = sbuf + NB * 288;
    float* smix = st2 + NB * 288;
    float* smsg = smix + NB * 288;
    float* sT   = smsg + NB * 288;
    int z0 = blockIdx.x * NB, tid = threadIdx.x;

    for (int o = tid; o < NB * 288; o += 256) {
        int n = o / 288, idx = o - n * 288;
        int slot = idx >> 5, u = idx & 31;
        float inv = 1.f / fmaxf(g_cnt[z0 + n], 1.f);
        sa[o] = g_asum[(z0 + n) * 288 + mergecol(u, slot)] * inv;
        smsg[o] = 0.f;
    }
    __syncthreads();
    lin_multi(sa, lin_o1, sbuf, false, tid); __syncthreads();
    lin_multi(sbuf, mixw, smix, false, tid); __syncthreads();
    lin_multi(smix, combw, smsg, true, tid); __syncthreads();
    for (int o = tid; o < NB * 288; o += 256) sbuf[o] = 0.f;
    __syncthreads();
    path_pair2<1>(sa, sa, o2w,          sbuf, sT, tid);
    path_pair2<2>(sa, sa, o2w + 32768,  sbuf, sT, tid);
    path_pair2<6>(sa, sa, o2w + 65536,  sbuf, sT, tid);
    path_uvu2<0> (sa, o2u,        sbuf, sT, tid);
    path_uvu2<4> (sa, o2u + 1024, sbuf, sT, tid);
    path_uvu2<5> (sa, o2u + 2048, sbuf, sT, tid);
    path_uvu2<9> (sa, o2u + 3072, sbuf, sT, tid);
    path_uvu2<10>(sa, o2u + 4096, sbuf, sT, tid);
    lin_multi(sbuf, mixw + 3072, smix, false, tid); __syncthreads();
    lin_multi(smix, combw + 3072, smsg, true, tid); __syncthreads();
    for (int o = tid; o < NB * 288; o += 256) st2[o] = 0.f;
    __syncthreads();
    path_pair2<0>(sa, sa, o3a,            st2, sT, tid);
    path_pair2<1>(sa, sa, o3a + 32768,    st2, sT, tid);
    path_pair2<2>(sa, sa, o3a + 65536,    st2, sT, tid);
    path_pair2<3>(sa, sa, o3a + 98304,    st2, sT, tid);
    path_pair2<4>(sa, sa, o3a + 131072,   st2, sT, tid);
    path_pair2<5>(sa, sa, o3a + 163840,   st2, sT, tid);
    path_pair2<6>(sa, sa, o3a + 196608,   st2, sT, tid);
    path_pair2<7>(sa, sa, o3a + 229376,   st2, sT, tid);
    path_pair2<8>(sa, sa, o3a + 262144,   st2, sT, tid);
    path_pair2<9>(sa, sa, o3a + 294912,   st2, sT, tid);
    path_pair2<10>(sa, sa, o3a + 327680,  st2, sT, tid);
    for (int o = tid; o < NB * 288; o += 256) sbuf[o] = 0.f;
    __syncthreads();
    path_pair2<0>(st2, sa, o3b,           sbuf, sT, tid);
    path_pair2<1>(st2, sa, o3b + 32768,   sbuf, sT, tid);
    path_pair2<2>(st2, sa, o3b + 65536,   sbuf, sT, tid);
    path_pair2<3>(st2, sa, o3b + 98304,   sbuf, sT, tid);
    path_pair2<4>(st2, sa, o3b + 131072,  sbuf, sT, tid);
    path_pair2<5>(st2, sa, o3b + 163840,  sbuf, sT, tid);
    path_pair2<6>(st2, sa, o3b + 196608,  sbuf, sT, tid);
    path_pair2<7>(st2, sa, o3b + 229376,  sbuf, sT, tid);
    path_pair2<8>(st2, sa, o3b + 262144,  sbuf, sT, tid);
    path_pair2<9>(st2, sa, o3b + 294912,  sbuf, sT, tid);
    path_pair2<10>(st2, sa, o3b + 327680, sbuf, sT, tid);
    lin_multi(sbuf, mixw + 6144, smix, false, tid); __syncthreads();
    lin_multi(smix, combw + 6144, smsg, true, tid); __syncthreads();
    if (tid < NB * 32) {
        int n = tid >> 5, w = tid & 31;
        const float* r = nf + (z0 + n) * 32;
        float s = 0.f;
#pragma unroll 8
        for (int v = 0; v < 32; v++) s += r[v] * __ldg(selfw + v * 32 + w);
        smsg[n * 288 + w] += s * (1.f / SQM);
    }
    __syncthreads();
    for (int o = tid; o < NB * 288; o += 256) {
        int n = o / 288, idx = o - n * 288;
        int slot = idx >> 5, u = idx & 31;
        out[(z0 + n) * 288 + mergecol(u, slot)] = smsg[o];
    }
}

/* -------------------- launch ---------------------------------------- */
extern "C" void kernel_launch(void* const* d_in, const int* in_sizes, int n_in,
                              void* d_out, int out_size) {
    const float* nf    = (const float*)d_in[0];
    const int*   ei    = (const int*)d_in[1];
    const float* sh    = (const float*)d_in[2];
    const float* rad   = (const float*)d_in[3];
    const float* attr  = (const float*)d_in[4];
    const float* w1    = (const float*)d_in[5];
    const float* b1    = (const float*)d_in[6];
    const float* w2    = (const float*)d_in[7];
    const float* b2    = (const float*)d_in[8];
    const float* w3    = (const float*)d_in[9];
    const float* b3    = (const float*)d_in[10];
    const float* aw    = (const float*)d_in[11];
    const float* ab    = (const float*)d_in[12];
    const float* emb   = (const float*)d_in[13];
    const float* lino1 = (const float*)d_in[14];
    const float* o2w   = (const float*)d_in[15];
    const float* o2u   = (const float*)d_in[16];
    const float* o3a   = (const float*)d_in[17];
    const float* o3b   = (const float*)d_in[18];
    const float* mixw  = (const float*)d_in[19];
    const float* combw = (const float*)d_in[20];
    const float* selfw = (const float*)d_in[21];

    cudaFuncSetAttribute(mace_node, cudaFuncAttributeMaxDynamicSharedMemorySize, SMEM_NODE_BYTES);

    mace_init<<<(N_NODES * 288 + 255) / 256, 256>>>(aw, ab);
    mace_front<<<8000 + 625, 512>>>(ei, rad, attr, w1, b1, w2, b2, w3, b3, nf, emb);
    mace_edge_gemm<<<N_EDGES / 64, 256>>>(ei, sh);
    mace_node<<<N_NODES / NB, 256, SMEM_NODE_BYTES>>>(nf, lino1, o2w, o2u, o3a, o3b,
                                                      mixw, combw, selfw, (float*)d_out);
}

// round 8
// speedup vs baseline: 2.1005x; 1.0197x over previous
#include <cuda_runtime.h>
#include <math.h>

#define N_NODES 10000
#define N_EDGES 64000
#define RHID 64
#define SQM 5.656854249492381f
#define NB 2
#define SMEM_NODE_BYTES 52480

__device__ float g_h[N_NODES * 32];
__device__ float g_rf[N_EDGES * RHID];
__device__ float g_A3[2080 * 96];
__device__ float g_asum[N_NODES * 288];
__device__ float g_cnt[N_NODES];
__device__ __align__(16) float g_WT[25 * 32768];   /* paired pair-path weights */
__device__ __align__(16) float g_LWT[21 * 1024];   /* paired linear weights    */

/* ---------------- packed fp32x2 helpers (Blackwell FFMA2) ----------- */
typedef unsigned long long u64t;
__device__ __forceinline__ u64t pack2(float a, float b) {
    u64t r; asm("mov.b64 %0,{%1,%2};" : "=l"(r) : "f"(a), "f"(b)); return r;
}
__device__ __forceinline__ u64t pack1(float a) { return pack2(a, a); }
__device__ __forceinline__ void unpack2(u64t p, float& a, float& b) {
    asm("mov.b64 {%0,%1},%2;" : "=f"(a), "=f"(b) : "l"(p));
}
__device__ __forceinline__ void fma2(u64t& d, u64t a, u64t b) {
    asm("fma.rn.f32x2 %0,%1,%2,%0;" : "+l"(d) : "l"(a), "l"(b));
}
__device__ __forceinline__ u64t mul2(u64t a, u64t b) {
    u64t r; asm("mul.rn.f32x2 %0,%1,%2;" : "=l"(r) : "l"(a), "l"(b)); return r;
}

/* ----------------- hardcoded Clebsch-Gordan tables ------------------ */
#define R3f   0.57735026918962576f
#define R5f   0.44721359549995794f
#define R10f  0.31622776601683794f
#define R30f  0.18257418583505536f
#define R30x2 0.36514837167011072f
#define CNA   0.20701966780270626f
#define CNB   0.23904572186687872f
#define CNC   0.11952286093343936f

template<int N> struct IC { static constexpr int v = N; };
#define T3(i,j,k,val) f(IC<i>{}, IC<j>{}, IC<k>{}, val)

template<int C> struct CGT;
template<> struct CGT<0> { static constexpr int DK=1,IB=0,JB=0,KB=0;
  template<class F> __device__ static void terms(F f){ T3(0,0,0,1.f); } };
template<> struct CGT<1> { static constexpr int DK=3,IB=0,JB=1,KB=1;
  template<class F> __device__ static void terms(F f){
    T3(0,0,0,R3f); T3(0,1,1,R3f); T3(0,2,2,R3f); } };
template<> struct CGT<2> { static constexpr int DK=5,IB=0,JB=4,KB=4;
  template<class F> __device__ static void terms(F f){
    T3(0,0,0,R5f); T3(0,1,1,R5f); T3(0,2,2,R5f); T3(0,3,3,R5f); T3(0,4,4,R5f); } };
template<> struct CGT<3> { static constexpr int DK=3,IB=1,JB=0,KB=1;
  template<class F> __device__ static void terms(F f){
    T3(0,0,0,R3f); T3(1,0,1,R3f); T3(2,0,2,R3f); } };
template<> struct CGT<4> { static constexpr int DK=1,IB=1,JB=1,KB=0;
  template<class F> __device__ static void terms(F f){
    T3(0,0,0,R3f); T3(1,1,0,R3f); T3(2,2,0,R3f); } };
template<> struct CGT<5> { static constexpr int DK=5,IB=1,JB=1,KB=4;
  template<class F> __device__ static void terms(F f){
    T3(0,1,0,R10f); T3(1,0,0,R10f); T3(1,2,1,R10f); T3(2,1,1,R10f);
    T3(0,0,2,-R30f); T3(1,1,2,-R30f); T3(2,2,2,R30x2);
    T3(0,2,3,R10f); T3(2,0,3,R10f); T3(0,0,4,R10f); T3(1,1,4,-R10f); } };
template<> struct CGT<6> { static constexpr int DK=3,IB=1,JB=4,KB=1;
  template<class F> __device__ static void terms(F f){
    T3(0,0,1,R10f); T3(1,0,0,R10f); T3(1,1,2,R10f); T3(2,1,1,R10f);
    T3(0,2,0,-R30f); T3(1,2,1,-R30f); T3(2,2,2,R30x2);
    T3(0,3,2,R10f); T3(2,3,0,R10f); T3(0,4,0,R10f); T3(1,4,1,-R10f); } };
template<> struct CGT<7> { static constexpr int DK=5,IB=4,JB=0,KB=4;
  template<class F> __device__ static void terms(F f){
    T3(0,0,0,R5f); T3(1,0,1,R5f); T3(2,0,2,R5f); T3(3,0,3,R5f); T3(4,0,4,R5f); } };
template<> struct CGT<8> { static constexpr int DK=3,IB=4,JB=1,KB=1;
  template<class F> __device__ static void terms(F f){
    T3(0,0,1,R10f); T3(0,1,0,R10f); T3(1,1,2,R10f); T3(1,2,1,R10f);
    T3(2,0,0,-R30f); T3(2,1,1,-R30f); T3(2,2,2,R30x2);
    T3(3,0,2,R10f); T3(3,2,0,R10f); T3(4,0,0,R10f); T3(4,1,1,-R10f); } };
template<> struct CGT<9> { static constexpr int DK=1,IB=4,JB=4,KB=0;
  template<class F> __device__ static void terms(F f){
    T3(0,0,0,R5f); T3(1,1,0,R5f); T3(2,2,0,R5f); T3(3,3,0,R5f); T3(4,4,0,R5f); } };
template<> struct CGT<10> { static constexpr int DK=5,IB=4,JB=4,KB=4;
  template<class F> __device__ static void terms(F f){
    T3(0,1,3,CNA); T3(0,3,1,CNA); T3(1,0,3,CNA); T3(1,3,0,CNA); T3(3,0,1,CNA); T3(3,1,0,CNA);
    T3(0,0,2,-CNB); T3(0,2,0,-CNB); T3(2,0,0,-CNB);
    T3(1,1,2,CNC); T3(1,2,1,CNC); T3(2,1,1,CNC);
    T3(3,3,2,CNC); T3(3,2,3,CNC); T3(2,3,3,CNC);
    T3(1,1,4,-CNA); T3(1,4,1,-CNA); T3(4,1,1,-CNA);
    T3(3,3,4,CNA); T3(3,4,3,CNA); T3(4,3,3,CNA);
    T3(2,2,2,CNB);
    T3(2,4,4,-CNB); T3(4,2,4,-CNB); T3(4,4,2,-CNB); } };

__device__ __forceinline__ int mergecol(int u, int slot) {
    if (slot == 0) return u;
    if (slot < 4)  return 32 + u * 3 + (slot - 1);
    return 128 + u * 5 + (slot - 4);
}

/* ----- fused init: zero + cnt + A3 repack + weight transposes ------- */
__global__ void mace_init(const float* __restrict__ aw, const float* __restrict__ ab,
                          const float* __restrict__ o2w, const float* __restrict__ o3a,
                          const float* __restrict__ o3b, const float* __restrict__ lino1,
                          const float* __restrict__ mixw, const float* __restrict__ combw) {
    int idx = blockIdx.x * blockDim.x + threadIdx.x;
    if (idx < N_NODES * 288) g_asum[idx] = 0.f;
    if (idx < N_NODES)       g_cnt[idx]  = 0.f;
    if (idx < 2080 * 96) {
        int k = idx / 96, n = idx - k * 96;
        int l = n >> 5, ww = n & 31;
        const float rsd[3] = {1.f, 0.57735026918962576f, 0.44721359549995794f};
        float scale = rsd[l] * (1.f / SQM);
        float v;
        if (k < 2048) { int r = k >> 5, u = k & 31; v = aw[r * 3072 + l * 1024 + u * 32 + ww]; }
        else          { int u = k - 2048;           v = ab[l * 1024 + u * 32 + ww]; }
        g_A3[idx] = v * scale;
    }
    if (idx < 25 * 32768) {               /* pair-path W transpose */
        int a = idx >> 15, r = idx & 32767;
        int q2 = r >> 6, t = r & 63;
        int w = t >> 1, b = t & 1;
        const float* src = (a < 3) ? (o2w + a * 32768)
                         : (a < 14) ? (o3a + (a - 3) * 32768)
                                    : (o3b + (a - 14) * 32768);
        g_WT[idx] = src[(2 * q2 + b) * 32 + w];
    }
    if (idx < 21 * 1024) {                /* linear W transpose */
        int a = idx >> 10, r = idx & 1023;
        int u2 = r >> 6, t = r & 63;
        int w = t >> 1, b = t & 1;
        const float* src = (a < 3) ? (lino1 + a * 1024)
                         : (a < 12) ? (mixw + (a - 3) * 1024)
                                    : (combw + (a - 12) * 1024);
        g_LWT[idx] = src[(2 * u2 + b) * 32 + w];
    }
}

/* ------------- fused front: edge MLP blocks + node-h blocks --------- */
__global__ __launch_bounds__(512) void mace_front(
    const int* __restrict__ ei, const float* __restrict__ rad, const float* __restrict__ attr,
    const float* __restrict__ w1, const float* __restrict__ b1,
    const float* __restrict__ w2, const float* __restrict__ b2,
    const float* __restrict__ w3, const float* __restrict__ b3,
    const float* __restrict__ nf, const float* __restrict__ emb) {
    __shared__ float w1s[24 * 64], w2s[64 * 64], w3s[64 * 64];
    __shared__ float b1s[64], b2s[64], b3s[64];
    __shared__ float rin[8][24], x1[8][64], x2[8][64];
    int tid = threadIdx.x;
    if (blockIdx.x >= 8000) {
        int z = (blockIdx.x - 8000) * 16 + (tid >> 5);
        int ww = tid & 31;
        const float* r = nf + z * 32;
        float s = 0.f;
#pragma unroll 8
        for (int u = 0; u < 32; u++) s += r[u] * emb[u * 32 + ww];
        g_h[z * 32 + ww] = s * (1.f / SQM);
        return;
    }
    for (int i = tid; i < 1536; i += 512) w1s[i] = w1[i];
    for (int i = tid; i < 4096; i += 512) { w2s[i] = w2[i]; w3s[i] = w3[i]; }
    if (tid < 64) { b1s[tid] = b1[tid]; b2s[tid] = b2[tid]; b3s[tid] = b3[tid]; }
    int eg = tid >> 6, t = tid & 63;
    int e = blockIdx.x * 8 + eg;
    if (t < 8)       rin[eg][t] = rad[e * 8 + t];
    else if (t < 24) rin[eg][t] = attr[e * 16 + (t - 8)];
    __syncthreads();
    float s = b1s[t];
#pragma unroll
    for (int k = 0; k < 24; k++) s += rin[eg][k] * w1s[k * 64 + t];
    s = s / (1.f + expf(-s));
    x1[eg][t] = s;
    __syncthreads();
    s = b2s[t];
#pragma unroll 8
    for (int k = 0; k < 64; k++) s += x1[eg][k] * w2s[k * 64 + t];
    s = s / (1.f + expf(-s));
    x2[eg][t] = s;
    __syncthreads();
    s = b3s[t];
#pragma unroll 8
    for (int k = 0; k < 64; k++) s += x2[eg][k] * w3s[k * 64 + t];
    g_rf[e * 64 + t] = s;
    if (t == 0) atomicAdd(&g_cnt[ei[N_EDGES + e]], 1.f);
}

/* ------------ fused edge GEMM (f32x2) + SH expand + scatter --------- */
__global__ __launch_bounds__(256) void mace_edge_gemm(
    const int* __restrict__ ei, const float* __restrict__ sh) {
    __shared__ int s_src[64], s_dst[64];
    __shared__ float s_sh[64 * 9];
    __shared__ __align__(8) float Hs2[32 * 64];
    __shared__ float RFs[64 * 64];
    __shared__ float At[32 * 96];
    int tid = threadIdx.x;
    int e0 = blockIdx.x * 64;
    for (int i = tid; i < 64; i += 256) { s_src[i] = ei[e0 + i]; s_dst[i] = ei[N_EDGES + e0 + i]; }
    for (int i = tid; i < 576; i += 256) s_sh[i] = sh[e0 * 9 + i];
    __syncthreads();
    for (int i = tid; i < 2048; i += 256) { int u = i >> 6, e = i & 63; Hs2[u * 64 + e] = g_h[s_src[e] * 32 + u]; }
    for (int i = tid; i < 4096; i += 256) { int e = i >> 6, r = i & 63; RFs[e * 64 + r] = g_rf[(e0 + e) * 64 + r]; }
    int tx = tid & 31, ty = tid >> 5;
    u64t acc2[4][3];
#pragma unroll
    for (int p = 0; p < 4; p++) { acc2[p][0] = pack2(0.f,0.f); acc2[p][1] = pack2(0.f,0.f); acc2[p][2] = pack2(0.f,0.f); }

    for (int kc = 0; kc < 2080; kc += 32) {
        __syncthreads();
        for (int i = tid; i < 3072; i += 256) {
            int kk = i / 96, n = i - kk * 96;
            At[i] = g_A3[(kc + kk) * 96 + n];
        }
        __syncthreads();
        bool bias = (kc >= 2048);
        int r = kc >> 5;
        u64t prf[4];
#pragma unroll
        for (int p = 0; p < 4; p++) {
            int e = ty * 8 + 2 * p;
            prf[p] = bias ? pack2(1.f, 1.f) : pack2(RFs[e * 64 + r], RFs[(e + 1) * 64 + r]);
        }
#pragma unroll 4
        for (int kk = 0; kk < 32; kk++) {
            u64t pa0 = pack1(At[kk * 96 + tx]);
            u64t pa1 = pack1(At[kk * 96 + 32 + tx]);
            u64t pa2 = pack1(At[kk * 96 + 64 + tx]);
            const u64t* hrow = (const u64t*)&Hs2[kk * 64 + ty * 8];
#pragma unroll
            for (int p = 0; p < 4; p++) {
                u64t pp = mul2(prf[p], hrow[p]);
                fma2(acc2[p][0], pp, pa0);
                fma2(acc2[p][1], pp, pa1);
                fma2(acc2[p][2], pp, pa2);
            }
        }
    }
    __syncthreads();
    float m[8][3];
#pragma unroll
    for (int p = 0; p < 4; p++)
#pragma unroll
        for (int c = 0; c < 3; c++) unpack2(acc2[p][c], m[2 * p][c], m[2 * p + 1][c]);
#pragma unroll
    for (int i = 0; i < 8; i++) {
        int e = ty * 8 + i;
        float* ob = &g_asum[s_dst[e] * 288];
        const float* shv = &s_sh[e * 9];
        atomicAdd(ob + tx, m[i][0] * shv[0]);
#pragma unroll
        for (int q = 0; q < 3; q++) atomicAdd(ob + 32 + tx * 3 + q, m[i][1] * shv[1 + q]);
#pragma unroll
        for (int q = 0; q < 5; q++) atomicAdd(ob + 128 + tx * 5 + q, m[i][2] * shv[4 + q]);
    }
}

/* ----------- per-node CG machinery (NB=2, slot-major layout) -------- */
template<int C>
__device__ __forceinline__ void stage1(const float* __restrict__ x, const float* __restrict__ y,
                                       float* __restrict__ sT, int tid) {
    constexpr int DK = CGT<C>::DK;
#pragma unroll
    for (int rep = 0; rep < NB * 2; rep++) {
        int idx = rep * 256 + tid;
        int n = idx >> 9, r = idx & 511;
        int u = r >> 4, v0 = (r & 15) * 2;
        const float* xr = x + n * 288 + CGT<C>::IB * 32 + u;
        const float* yr = y + n * 288 + CGT<C>::JB * 32 + v0;
        u64t acc[DK];
#pragma unroll
        for (int kk = 0; kk < DK; kk++) acc[kk] = pack2(0.f, 0.f);
        CGT<C>::terms([&](auto ti, auto tj, auto tk, float val) {
            u64t px = pack1(xr[ti.v * 32] * val);
            u64t py = *(const u64t*)&yr[tj.v * 32];
            fma2(acc[tk.v], px, py);
        });
#pragma unroll
        for (int kk = 0; kk < DK; kk++)
            *(u64t*)&sT[(n * DK + kk) * 1024 + u * 32 + v0] = acc[kk];
    }
}

template<int C>
__device__ void path_pair2(const float* __restrict__ x, const float* __restrict__ y,
                           int path, float* __restrict__ out,
                           float* __restrict__ sT, int tid) {
    constexpr int DK = CGT<C>::DK;
    stage1<C>(x, y, sT, tid);
    __syncthreads();
    int g = tid >> 5, w = tid & 31;
    u64t part[NB][DK];
#pragma unroll
    for (int n = 0; n < NB; n++)
#pragma unroll
        for (int kk = 0; kk < DK; kk++) part[n][kk] = pack2(0.f, 0.f);
    const u64t* Wg = (const u64t*)g_WT + path * 16384 + w;
#pragma unroll 2
    for (int q = 0; q < 128; q += 4) {
        int q2 = g * 64 + (q >> 1);
        u64t pwA = __ldg(Wg + q2 * 32);
        u64t pwB = __ldg(Wg + q2 * 32 + 32);
        int base = g * 128 + q;
#pragma unroll
        for (int n = 0; n < NB; n++)
#pragma unroll
            for (int kk = 0; kk < DK; kk++) {
                longlong2 tv = *(const longlong2*)&sT[(n * DK + kk) * 1024 + base];
                fma2(part[n][kk], (u64t)tv.x, pwA);
                fma2(part[n][kk], (u64t)tv.y, pwB);
            }
    }
#pragma unroll
    for (int n = 0; n < NB; n++)
#pragma unroll
        for (int kk = 0; kk < DK; kk++) {
            float lo, hi;
            unpack2(part[n][kk], lo, hi);
            atomicAdd(&out[n * 288 + (CGT<C>::KB + kk) * 32 + w], (lo + hi) * (1.f / 32.f));
        }
    __syncthreads();
}

template<int C>
__device__ void path_uvu2(const float* __restrict__ x, const float* __restrict__ Wp,
                          float* __restrict__ out, float* __restrict__ sT, int tid) {
    constexpr int DK = CGT<C>::DK;
    stage1<C>(x, x, sT, tid);
    __syncthreads();
    for (int o = tid; o < NB * 32 * DK; o += 256) {
        int n = o / (32 * DK);
        int r = o - n * 32 * DK;
        int u = r / DK, kk = r - u * DK;
        const u64t* Tp = (const u64t*)&sT[(n * DK + kk) * 1024 + u * 32];
        const float* Wr = Wp + u * 32;
        u64t accp = pack2(0.f, 0.f);
#pragma unroll 8
        for (int v2 = 0; v2 < 16; v2++) {
            u64t wv = *(const u64t*)&Wr[v2 * 2];
            fma2(accp, Tp[v2], wv);
        }
        float lo, hi; unpack2(accp, lo, hi);
        out[n * 288 + (CGT<C>::KB + kk) * 32 + u] += (lo + hi) * (1.f / SQM);
    }
    __syncthreads();
}

__device__ void lin_multi(const float* in, int wbase, float* out, bool accum, int tid) {
    for (int o = tid; o < NB * 288; o += 256) {
        int n = o / 288, idx = o - n * 288;
        int slot = idx >> 5, ww = idx & 31;
        int l = (slot == 0) ? 0 : (slot < 4 ? 1 : 2);
        const u64t* Wl = (const u64t*)g_LWT + (wbase + l) * 512 + ww;
        const u64t* ib = (const u64t*)(in + n * 288 + slot * 32);
        u64t accp = pack2(0.f, 0.f);
#pragma unroll 8
        for (int u2 = 0; u2 < 16; u2++)
            fma2(accp, ib[u2], __ldg(Wl + u2 * 32));
        float lo, hi; unpack2(accp, lo, hi);
        float s = (lo + hi) * (1.f / SQM);
        if (accum) out[o] += s; else out[o] = s;
    }
}

/* -------------------- per-node main kernel (NB=2) ------------------- */
__global__ __launch_bounds__(256, 4) void mace_node(
    const float* __restrict__ nf, const float* __restrict__ o2u,
    const float* __restrict__ selfw, float* __restrict__ out) {
    extern __shared__ float smem[];
    float* sa   = smem;
    float* sbuf = sa + NB * 288;
    float* st2  = sbuf + NB * 288;
    float* smix = st2 + NB * 288;
    float* smsg = smix + NB * 288;
    float* sT   = smsg + NB * 288;
    int z0 = blockIdx.x * NB, tid = threadIdx.x;

    for (int o = tid; o < NB * 288; o += 256) {
        int n = o / 288, idx = o - n * 288;
        int slot = idx >> 5, u = idx & 31;
        float inv = 1.f / fmaxf(g_cnt[z0 + n], 1.f);
        sa[o] = g_asum[(z0 + n) * 288 + mergecol(u, slot)] * inv;
        smsg[o] = 0.f;
    }
    __syncthreads();
    lin_multi(sa, 0, sbuf, false, tid);  __syncthreads();
    lin_multi(sbuf, 3, smix, false, tid); __syncthreads();
    lin_multi(smix, 12, smsg, true, tid); __syncthreads();
    for (int o = tid; o < NB * 288; o += 256) sbuf[o] = 0.f;
    __syncthreads();
    path_pair2<1>(sa, sa, 0, sbuf, sT, tid);
    path_pair2<2>(sa, sa, 1, sbuf, sT, tid);
    path_pair2<6>(sa, sa, 2, sbuf, sT, tid);
    path_uvu2<0> (sa, o2u,        sbuf, sT, tid);
    path_uvu2<4> (sa, o2u + 1024, sbuf, sT, tid);
    path_uvu2<5> (sa, o2u + 2048, sbuf, sT, tid);
    path_uvu2<9> (sa, o2u + 3072, sbuf, sT, tid);
    path_uvu2<10>(sa, o2u + 4096, sbuf, sT, tid);
    lin_multi(sbuf, 6, smix, false, tid); __syncthreads();
    lin_multi(smix, 15, smsg, true, tid); __syncthreads();
    for (int o = tid; o < NB * 288; o += 256) st2[o] = 0.f;
    __syncthreads();
    path_pair2<0>(sa, sa, 3,  st2, sT, tid);
    path_pair2<1>(sa, sa, 4,  st2, sT, tid);
    path_pair2<2>(sa, sa, 5,  st2, sT, tid);
    path_pair2<3>(sa, sa, 6,  st2, sT, tid);
    path_pair2<4>(sa, sa, 7,  st2, sT, tid);
    path_pair2<5>(sa, sa, 8,  st2, sT, tid);
    path_pair2<6>(sa, sa, 9,  st2, sT, tid);
    path_pair2<7>(sa, sa, 10, st2, sT, tid);
    path_pair2<8>(sa, sa, 11, st2, sT, tid);
    path_pair2<9>(sa, sa, 12, st2, sT, tid);
    path_pair2<10>(sa, sa, 13, st2, sT, tid);
    for (int o = tid; o < NB * 288; o += 256) sbuf[o] = 0.f;
    __syncthreads();
    path_pair2<0>(st2, sa, 14, sbuf, sT, tid);
    path_pair2<1>(st2, sa, 15, sbuf, sT, tid);
    path_pair2<2>(st2, sa, 16, sbuf, sT, tid);
    path_pair2<3>(st2, sa, 17, sbuf, sT, tid);
    path_pair2<4>(st2, sa, 18, sbuf, sT, tid);
    path_pair2<5>(st2, sa, 19, sbuf, sT, tid);
    path_pair2<6>(st2, sa, 20, sbuf, sT, tid);
    path_pair2<7>(st2, sa, 21, sbuf, sT, tid);
    path_pair2<8>(st2, sa, 22, sbuf, sT, tid);
    path_pair2<9>(st2, sa, 23, sbuf, sT, tid);
    path_pair2<10>(st2, sa, 24, sbuf, sT, tid);
    lin_multi(sbuf, 9, smix, false, tid); __syncthreads();
    lin_multi(smix, 18, smsg, true, tid); __syncthreads();
    if (tid < NB * 32) {
        int n = tid >> 5, w = tid & 31;
        const float* r = nf + (z0 + n) * 32;
        float s = 0.f;
#pragma unroll 8
        for (int v = 0; v < 32; v++) s += r[v] * __ldg(selfw + v * 32 + w);
        smsg[n * 288 + w] += s * (1.f / SQM);
    }
    __syncthreads();
    for (int o = tid; o < NB * 288; o += 256) {
        int n = o / 288, idx = o - n * 288;
        int slot = idx >> 5, u = idx & 31;
        out[(z0 + n) * 288 + mergecol(u, slot)] = smsg[o];
    }
}

/* -------------------- launch ---------------------------------------- */
extern "C" void kernel_launch(void* const* d_in, const int* in_sizes, int n_in,
                              void* d_out, int out_size) {
    const float* nf    = (const float*)d_in[0];
    const int*   ei    = (const int*)d_in[1];
    const float* sh    = (const float*)d_in[2];
    const float* rad   = (const float*)d_in[3];
    const float* attr  = (const float*)d_in[4];
    const float* w1    = (const float*)d_in[5];
    const float* b1    = (const float*)d_in[6];
    const float* w2    = (const float*)d_in[7];
    const float* b2    = (const float*)d_in[8];
    const float* w3    = (const float*)d_in[9];
    const float* b3    = (const float*)d_in[10];
    const float* aw    = (const float*)d_in[11];
    const float* ab    = (const float*)d_in[12];
    const float* emb   = (const float*)d_in[13];
    const float* lino1 = (const float*)d_in[14];
    const float* o2w   = (const float*)d_in[15];
    const float* o2u   = (const float*)d_in[16];
    const float* o3a   = (const float*)d_in[17];
    const float* o3b   = (const float*)d_in[18];
    const float* mixw  = (const float*)d_in[19];
    const float* combw = (const float*)d_in[20];
    const float* selfw = (const float*)d_in[21];

    cudaFuncSetAttribute(mace_node, cudaFuncAttributeMaxDynamicSharedMemorySize, SMEM_NODE_BYTES);

    mace_init<<<(N_NODES * 288 + 255) / 256, 256>>>(aw, ab, o2w, o3a, o3b, lino1, mixw, combw);
    mace_front<<<8000 + 625, 512>>>(ei, rad, attr, w1, b1, w2, b2, w3, b3, nf, emb);
    mace_edge_gemm<<<N_EDGES / 64, 256>>>(ei, sh);
    mace_node<<<N_NODES / NB, 256, SMEM_NODE_BYTES>>>(nf, o2u, selfw, (float*)d_out);
}

// round 9
// speedup vs baseline: 2.9733x; 1.4155x over previous
#include <cuda_runtime.h>
#include <math.h>

#define N_NODES 10000
#define N_EDGES 64000
#define RHID 64
#define SQM 5.656854249492381f
#define NB 2
#define SMEM_NODE_BYTES 11776

__device__ float g_h[N_NODES * 32];
__device__ float g_rf[N_EDGES * RHID];
__device__ float g_A3[2080 * 96];
__device__ float g_asum[N_NODES * 288];
__device__ float g_cnt[N_NODES];
__device__ __align__(16) float g_WT[25 * 32768];    /* v-pair-major weights */
__device__ __align__(16) float g_WT2[25 * 32768];   /* u-pair-major weights */
__device__ __align__(16) float g_LWT[21 * 1024];    /* paired linear weights */

/* ---------------- packed fp32x2 helpers (Blackwell FFMA2) ----------- */
typedef unsigned long long u64t;
__device__ __forceinline__ u64t pack2(float a, float b) {
    u64t r; asm("mov.b64 %0,{%1,%2};" : "=l"(r) : "f"(a), "f"(b)); return r;
}
__device__ __forceinline__ u64t pack1(float a) { return pack2(a, a); }
__device__ __forceinline__ void unpack2(u64t p, float& a, float& b) {
    asm("mov.b64 {%0,%1},%2;" : "=f"(a), "=f"(b) : "l"(p));
}
__device__ __forceinline__ void fma2(u64t& d, u64t a, u64t b) {
    asm("fma.rn.f32x2 %0,%1,%2,%0;" : "+l"(d) : "l"(a), "l"(b));
}
__device__ __forceinline__ u64t mul2(u64t a, u64t b) {
    u64t r; asm("mul.rn.f32x2 %0,%1,%2;" : "=l"(r) : "l"(a), "l"(b)); return r;
}

/* ----------------- hardcoded Clebsch-Gordan tables ------------------ */
#define R3f   0.57735026918962576f
#define R5f   0.44721359549995794f
#define R10f  0.31622776601683794f
#define R30f  0.18257418583505536f
#define R30x2 0.36514837167011072f
#define CNA   0.20701966780270626f
#define CNB   0.23904572186687872f
#define CNC   0.11952286093343936f

template<int N> struct IC { static constexpr int v = N; };
#define T3(i,j,k,val) f(IC<i>{}, IC<j>{}, IC<k>{}, val)

template<int C> struct CGT;
template<> struct CGT<0> { static constexpr int DK=1,IB=0,JB=0,KB=0;
  template<class F> __device__ static void terms(F f){ T3(0,0,0,1.f); } };
template<> struct CGT<1> { static constexpr int DK=3,IB=0,JB=1,KB=1;
  template<class F> __device__ static void terms(F f){
    T3(0,0,0,R3f); T3(0,1,1,R3f); T3(0,2,2,R3f); } };
template<> struct CGT<2> { static constexpr int DK=5,IB=0,JB=4,KB=4;
  template<class F> __device__ static void terms(F f){
    T3(0,0,0,R5f); T3(0,1,1,R5f); T3(0,2,2,R5f); T3(0,3,3,R5f); T3(0,4,4,R5f); } };
template<> struct CGT<3> { static constexpr int DK=3,IB=1,JB=0,KB=1;
  template<class F> __device__ static void terms(F f){
    T3(0,0,0,R3f); T3(1,0,1,R3f); T3(2,0,2,R3f); } };
template<> struct CGT<4> { static constexpr int DK=1,IB=1,JB=1,KB=0;
  template<class F> __device__ static void terms(F f){
    T3(0,0,0,R3f); T3(1,1,0,R3f); T3(2,2,0,R3f); } };
template<> struct CGT<5> { static constexpr int DK=5,IB=1,JB=1,KB=4;
  template<class F> __device__ static void terms(F f){
    T3(0,1,0,R10f); T3(1,0,0,R10f); T3(1,2,1,R10f); T3(2,1,1,R10f);
    T3(0,0,2,-R30f); T3(1,1,2,-R30f); T3(2,2,2,R30x2);
    T3(0,2,3,R10f); T3(2,0,3,R10f); T3(0,0,4,R10f); T3(1,1,4,-R10f); } };
template<> struct CGT<6> { static constexpr int DK=3,IB=1,JB=4,KB=1;
  template<class F> __device__ static void terms(F f){
    T3(0,0,1,R10f); T3(1,0,0,R10f); T3(1,1,2,R10f); T3(2,1,1,R10f);
    T3(0,2,0,-R30f); T3(1,2,1,-R30f); T3(2,2,2,R30x2);
    T3(0,3,2,R10f); T3(2,3,0,R10f); T3(0,4,0,R10f); T3(1,4,1,-R10f); } };
template<> struct CGT<7> { static constexpr int DK=5,IB=4,JB=0,KB=4;
  template<class F> __device__ static void terms(F f){
    T3(0,0,0,R5f); T3(1,0,1,R5f); T3(2,0,2,R5f); T3(3,0,3,R5f); T3(4,0,4,R5f); } };
template<> struct CGT<8> { static constexpr int DK=3,IB=4,JB=1,KB=1;
  template<class F> __device__ static void terms(F f){
    T3(0,0,1,R10f); T3(0,1,0,R10f); T3(1,1,2,R10f); T3(1,2,1,R10f);
    T3(2,0,0,-R30f); T3(2,1,1,-R30f); T3(2,2,2,R30x2);
    T3(3,0,2,R10f); T3(3,2,0,R10f); T3(4,0,0,R10f); T3(4,1,1,-R10f); } };
template<> struct CGT<9> { static constexpr int DK=1,IB=4,JB=4,KB=0;
  template<class F> __device__ static void terms(F f){
    T3(0,0,0,R5f); T3(1,1,0,R5f); T3(2,2,0,R5f); T3(3,3,0,R5f); T3(4,4,0,R5f); } };
template<> struct CGT<10> { static constexpr int DK=5,IB=4,JB=4,KB=4;
  template<class F> __device__ static void terms(F f){
    T3(0,1,3,CNA); T3(0,3,1,CNA); T3(1,0,3,CNA); T3(1,3,0,CNA); T3(3,0,1,CNA); T3(3,1,0,CNA);
    T3(0,0,2,-CNB); T3(0,2,0,-CNB); T3(2,0,0,-CNB);
    T3(1,1,2,CNC); T3(1,2,1,CNC); T3(2,1,1,CNC);
    T3(3,3,2,CNC); T3(3,2,3,CNC); T3(2,3,3,CNC);
    T3(1,1,4,-CNA); T3(1,4,1,-CNA); T3(4,1,1,-CNA);
    T3(3,3,4,CNA); T3(3,4,3,CNA); T3(4,3,3,CNA);
    T3(2,2,2,CNB);
    T3(2,4,4,-CNB); T3(4,2,4,-CNB); T3(4,4,2,-CNB); } };

__device__ __forceinline__ int mergecol(int u, int slot) {
    if (slot == 0) return u;
    if (slot < 4)  return 32 + u * 3 + (slot - 1);
    return 128 + u * 5 + (slot - 4);
}

/* ----- fused init: zero + cnt + A3 repack + weight transposes ------- */
__global__ void mace_init(const float* __restrict__ aw, const float* __restrict__ ab,
                          const float* __restrict__ o2w, const float* __restrict__ o3a,
                          const float* __restrict__ o3b, const float* __restrict__ lino1,
                          const float* __restrict__ mixw, const float* __restrict__ combw) {
    int idx = blockIdx.x * blockDim.x + threadIdx.x;
    if (idx < N_NODES * 288) g_asum[idx] = 0.f;
    if (idx < N_NODES)       g_cnt[idx]  = 0.f;
    if (idx < 2080 * 96) {
        int k = idx / 96, n = idx - k * 96;
        int l = n >> 5, ww = n & 31;
        const float rsd[3] = {1.f, 0.57735026918962576f, 0.44721359549995794f};
        float scale = rsd[l] * (1.f / SQM);
        float v;
        if (k < 2048) { int r = k >> 5, u = k & 31; v = aw[r * 3072 + l * 1024 + u * 32 + ww]; }
        else          { int u = k - 2048;           v = ab[l * 1024 + u * 32 + ww]; }
        g_A3[idx] = v * scale;
    }
    if (idx < 25 * 32768) {
        int a = idx >> 15, r = idx & 32767;
        int q2 = r >> 6, t = r & 63;
        int w = t >> 1, b = t & 1;
        const float* src = (a < 3) ? (o2w + a * 32768)
                         : (a < 14) ? (o3a + (a - 3) * 32768)
                                    : (o3b + (a - 14) * 32768);
        g_WT[idx] = src[(2 * q2 + b) * 32 + w];          /* pair over v */
        int v2 = q2 >> 4, up = q2 & 15;                  /* pair over u */
        g_WT2[idx] = src[((2 * up + b) * 32 + v2) * 32 + w];
    }
    if (idx < 21 * 1024) {
        int a = idx >> 10, r = idx & 1023;
        int u2 = r >> 6, t = r & 63;
        int w = t >> 1, b = t & 1;
        const float* src = (a < 3) ? (lino1 + a * 1024)
                         : (a < 12) ? (mixw + (a - 3) * 1024)
                                    : (combw + (a - 12) * 1024);
        g_LWT[idx] = src[(2 * u2 + b) * 32 + w];
    }
}

/* ------------- fused front: edge MLP blocks + node-h blocks --------- */
__global__ __launch_bounds__(512) void mace_front(
    const int* __restrict__ ei, const float* __restrict__ rad, const float* __restrict__ attr,
    const float* __restrict__ w1, const float* __restrict__ b1,
    const float* __restrict__ w2, const float* __restrict__ b2,
    const float* __restrict__ w3, const float* __restrict__ b3,
    const float* __restrict__ nf, const float* __restrict__ emb) {
    __shared__ float w1s[24 * 64], w2s[64 * 64], w3s[64 * 64];
    __shared__ float b1s[64], b2s[64], b3s[64];
    __shared__ float rin[8][24], x1[8][64], x2[8][64];
    int tid = threadIdx.x;
    if (blockIdx.x >= 8000) {
        int z = (blockIdx.x - 8000) * 16 + (tid >> 5);
        int ww = tid & 31;
        const float* r = nf + z * 32;
        float s = 0.f;
#pragma unroll 8
        for (int u = 0; u < 32; u++) s += r[u] * emb[u * 32 + ww];
        g_h[z * 32 + ww] = s * (1.f / SQM);
        return;
    }
    for (int i = tid; i < 1536; i += 512) w1s[i] = w1[i];
    for (int i = tid; i < 4096; i += 512) { w2s[i] = w2[i]; w3s[i] = w3[i]; }
    if (tid < 64) { b1s[tid] = b1[tid]; b2s[tid] = b2[tid]; b3s[tid] = b3[tid]; }
    int eg = tid >> 6, t = tid & 63;
    int e = blockIdx.x * 8 + eg;
    if (t < 8)       rin[eg][t] = rad[e * 8 + t];
    else if (t < 24) rin[eg][t] = attr[e * 16 + (t - 8)];
    __syncthreads();
    float s = b1s[t];
#pragma unroll
    for (int k = 0; k < 24; k++) s += rin[eg][k] * w1s[k * 64 + t];
    s = s / (1.f + expf(-s));
    x1[eg][t] = s;
    __syncthreads();
    s = b2s[t];
#pragma unroll 8
    for (int k = 0; k < 64; k++) s += x1[eg][k] * w2s[k * 64 + t];
    s = s / (1.f + expf(-s));
    x2[eg][t] = s;
    __syncthreads();
    s = b3s[t];
#pragma unroll 8
    for (int k = 0; k < 64; k++) s += x2[eg][k] * w3s[k * 64 + t];
    g_rf[e * 64 + t] = s;
    if (t == 0) atomicAdd(&g_cnt[ei[N_EDGES + e]], 1.f);
}

/* ------------ fused edge GEMM (f32x2) + SH expand + scatter --------- */
__global__ __launch_bounds__(256) void mace_edge_gemm(
    const int* __restrict__ ei, const float* __restrict__ sh) {
    __shared__ int s_src[64], s_dst[64];
    __shared__ float s_sh[64 * 9];
    __shared__ __align__(8) float Hs2[32 * 64];
    __shared__ float RFs[64 * 64];
    __shared__ float At[32 * 96];
    int tid = threadIdx.x;
    int e0 = blockIdx.x * 64;
    for (int i = tid; i < 64; i += 256) { s_src[i] = ei[e0 + i]; s_dst[i] = ei[N_EDGES + e0 + i]; }
    for (int i = tid; i < 576; i += 256) s_sh[i] = sh[e0 * 9 + i];
    __syncthreads();
    for (int i = tid; i < 2048; i += 256) { int u = i >> 6, e = i & 63; Hs2[u * 64 + e] = g_h[s_src[e] * 32 + u]; }
    for (int i = tid; i < 4096; i += 256) { int e = i >> 6, r = i & 63; RFs[e * 64 + r] = g_rf[(e0 + e) * 64 + r]; }
    int tx = tid & 31, ty = tid >> 5;
    u64t acc2[4][3];
#pragma unroll
    for (int p = 0; p < 4; p++) { acc2[p][0] = 0ull; acc2[p][1] = 0ull; acc2[p][2] = 0ull; }

    for (int kc = 0; kc < 2080; kc += 32) {
        __syncthreads();
        for (int i = tid; i < 3072; i += 256) {
            int kk = i / 96, n = i - kk * 96;
            At[i] = g_A3[(kc + kk) * 96 + n];
        }
        __syncthreads();
        bool bias = (kc >= 2048);
        int r = kc >> 5;
        u64t prf[4];
#pragma unroll
        for (int p = 0; p < 4; p++) {
            int e = ty * 8 + 2 * p;
            prf[p] = bias ? pack2(1.f, 1.f) : pack2(RFs[e * 64 + r], RFs[(e + 1) * 64 + r]);
        }
#pragma unroll 4
        for (int kk = 0; kk < 32; kk++) {
            u64t pa0 = pack1(At[kk * 96 + tx]);
            u64t pa1 = pack1(At[kk * 96 + 32 + tx]);
            u64t pa2 = pack1(At[kk * 96 + 64 + tx]);
            const u64t* hrow = (const u64t*)&Hs2[kk * 64 + ty * 8];
#pragma unroll
            for (int p = 0; p < 4; p++) {
                u64t pp = mul2(prf[p], hrow[p]);
                fma2(acc2[p][0], pp, pa0);
                fma2(acc2[p][1], pp, pa1);
                fma2(acc2[p][2], pp, pa2);
            }
        }
    }
    __syncthreads();
    float m[8][3];
#pragma unroll
    for (int p = 0; p < 4; p++)
#pragma unroll
        for (int c = 0; c < 3; c++) unpack2(acc2[p][c], m[2 * p][c], m[2 * p + 1][c]);
#pragma unroll
    for (int i = 0; i < 8; i++) {
        int e = ty * 8 + i;
        float* ob = &g_asum[s_dst[e] * 288];
        const float* shv = &s_sh[e * 9];
        atomicAdd(ob + tx, m[i][0] * shv[0]);
#pragma unroll
        for (int q = 0; q < 3; q++) atomicAdd(ob + 32 + tx * 3 + q, m[i][1] * shv[1 + q]);
#pragma unroll
        for (int q = 0; q < 5; q++) atomicAdd(ob + 128 + tx * 5 + q, m[i][2] * shv[4 + q]);
    }
}

/* ---- per-node pair path: register-resident P, no T intermediate ---- */
template<int C, bool SWAP, int UCHUNK, bool NSPLIT>
__device__ void path_pair3(const float* __restrict__ x, const float* __restrict__ y,
                           int path, float* __restrict__ out, int tid) {
    constexpr int DK = CGT<C>::DK;
    constexpr int INSLOT  = SWAP ? CGT<C>::IB : CGT<C>::JB;
    constexpr int OUTSLOT = SWAP ? CGT<C>::JB : CGT<C>::IB;
    constexpr int DIN  = (INSLOT == 0) ? 1 : ((INSLOT == 1) ? 3 : 5);
    constexpr int DOUT = (OUTSLOT == 0) ? 1 : ((OUTSLOT == 1) ? 3 : 5);
    constexpr int NBP  = NSPLIT ? 1 : NB;
    constexpr int NCH  = 4 / UCHUNK;
    int g = tid >> 5, w = tid & 31;
    const float* innb = SWAP ? x : y;
    const float* outbp = SWAP ? y : x;
    const u64t* Wb = (const u64t*)(SWAP ? g_WT2 : g_WT) + path * 16384 + w;
    u64t acc2[NB][DK];
#pragma unroll
    for (int n = 0; n < NB; n++)
#pragma unroll
        for (int kk = 0; kk < DK; kk++) acc2[n][kk] = 0ull;

    for (int nl = 0; nl < (NSPLIT ? NB : 1); nl++) {
#pragma unroll
        for (int ch = 0; ch < NCH; ch++) {
            int a0 = g * 4 + ch * UCHUNK;
            u64t P[NBP][UCHUNK][DIN];
#pragma unroll
            for (int nn = 0; nn < NBP; nn++)
#pragma unroll
                for (int uc = 0; uc < UCHUNK; uc++)
#pragma unroll
                    for (int jm = 0; jm < DIN; jm++) P[nn][uc][jm] = 0ull;
#pragma unroll 4
            for (int bp = 0; bp < 16; bp++) {
                u64t in2[NBP][DIN];
#pragma unroll
                for (int nn = 0; nn < NBP; nn++) {
                    int node = NSPLIT ? nl : nn;
#pragma unroll
                    for (int jm = 0; jm < DIN; jm++)
                        in2[nn][jm] = *(const u64t*)&innb[node * 288 + (INSLOT + jm) * 32 + 2 * bp];
                }
#pragma unroll
                for (int uc = 0; uc < UCHUNK; uc++) {
                    u64t wv = __ldg(Wb + ((a0 + uc) * 16 + bp) * 32);
#pragma unroll
                    for (int nn = 0; nn < NBP; nn++)
#pragma unroll
                        for (int jm = 0; jm < DIN; jm++)
                            fma2(P[nn][uc][jm], in2[nn][jm], wv);
                }
            }
#pragma unroll
            for (int uc = 0; uc < UCHUNK; uc++) {
                int a = a0 + uc;
                float os[NBP][DOUT];
#pragma unroll
                for (int nn = 0; nn < NBP; nn++) {
                    int node = NSPLIT ? nl : nn;
#pragma unroll
                    for (int im = 0; im < DOUT; im++)
                        os[nn][im] = outbp[node * 288 + (OUTSLOT + im) * 32 + a];
                }
                CGT<C>::terms([&](auto ti, auto tj, auto tk, float val) {
                    constexpr int OI = SWAP ? decltype(tj)::v : decltype(ti)::v;
                    constexpr int PI = SWAP ? decltype(ti)::v : decltype(tj)::v;
#pragma unroll
                    for (int nn = 0; nn < NBP; nn++) {
                        int node = NSPLIT ? nl : nn;
                        fma2(acc2[node][decltype(tk)::v], pack1(os[nn][OI] * val), P[nn][uc][PI]);
                    }
                });
            }
        }
    }
#pragma unroll
    for (int n = 0; n < NB; n++)
#pragma unroll
        for (int kk = 0; kk < DK; kk++) {
            float lo, hi;
            unpack2(acc2[n][kk], lo, hi);
            atomicAdd(&out[n * 288 + (CGT<C>::KB + kk) * 32 + w], (lo + hi) * (1.f / 32.f));
        }
}

/* ---- uvu path: per-(n,u) register Q, no intermediate ---------------- */
template<int C>
__device__ void path_uvu3(const float* __restrict__ x, const float* __restrict__ Wp,
                          float* __restrict__ out, int tid) {
    constexpr int DK = CGT<C>::DK;
    constexpr int IBv = CGT<C>::IB, JBv = CGT<C>::JB;
    constexpr int DJ = (JBv == 0) ? 1 : ((JBv == 1) ? 3 : 5);
    if (tid < NB * 32) {
        int n = tid >> 5, u = tid & 31;
        const float* xb = x + n * 288;
        const u64t* Wr = (const u64t*)(Wp + u * 32);
        u64t Q[DJ];
#pragma unroll
        for (int jm = 0; jm < DJ; jm++) Q[jm] = 0ull;
#pragma unroll
        for (int vp = 0; vp < 16; vp++) {
            u64t wv = __ldg(Wr + vp);
#pragma unroll
            for (int jm = 0; jm < DJ; jm++)
                fma2(Q[jm], *(const u64t*)&xb[(JBv + jm) * 32 + 2 * vp], wv);
        }
        float Qs[DJ];
#pragma unroll
        for (int jm = 0; jm < DJ; jm++) { float lo, hi; unpack2(Q[jm], lo, hi); Qs[jm] = lo + hi; }
        float accs[DK];
#pragma unroll
        for (int kk = 0; kk < DK; kk++) accs[kk] = 0.f;
        CGT<C>::terms([&](auto ti, auto tj, auto tk, float val) {
            accs[decltype(tk)::v] += val * xb[(IBv + decltype(ti)::v) * 32 + u] * Qs[decltype(tj)::v];
        });
#pragma unroll
        for (int kk = 0; kk < DK; kk++)
            atomicAdd(&out[n * 288 + (CGT<C>::KB + kk) * 32 + u], accs[kk] * (1.f / SQM));
    }
}

__device__ void lin_multi(const float* in, int wbase, float* out, bool accum, int tid) {
    for (int o = tid; o < NB * 288; o += 256) {
        int n = o / 288, idx = o - n * 288;
        int slot = idx >> 5, ww = idx & 31;
        int l = (slot == 0) ? 0 : (slot < 4 ? 1 : 2);
        const u64t* Wl = (const u64t*)g_LWT + (wbase + l) * 512 + ww;
        const u64t* ib = (const u64t*)(in + n * 288 + slot * 32);
        u64t accp = 0ull;
#pragma unroll 8
        for (int u2 = 0; u2 < 16; u2++)
            fma2(accp, ib[u2], __ldg(Wl + u2 * 32));
        float lo, hi; unpack2(accp, lo, hi);
        float s = (lo + hi) * (1.f / SQM);
        if (accum) out[o] += s; else out[o] = s;
    }
}

/* -------------------- per-node main kernel (NB=2) ------------------- */
__global__ __launch_bounds__(256, 4) void mace_node(
    const float* __restrict__ nf, const float* __restrict__ o2u,
    const float* __restrict__ selfw, float* __restrict__ out) {
    extern __shared__ float smem[];
    float* sa   = smem;
    float* sbuf = sa + NB * 288;
    float* st2  = sbuf + NB * 288;
    float* smix = st2 + NB * 288;
    float* smsg = smix + NB * 288;
    int z0 = blockIdx.x * NB, tid = threadIdx.x;

    for (int o = tid; o < NB * 288; o += 256) {
        int n = o / 288, idx = o - n * 288;
        int slot = idx >> 5, u = idx & 31;
        float inv = 1.f / fmaxf(g_cnt[z0 + n], 1.f);
        sa[o] = g_asum[(z0 + n) * 288 + mergecol(u, slot)] * inv;
        smsg[o] = 0.f;
        sbuf[o] = 0.f;
    }
    __syncthreads();
    /* order 0 */
    lin_multi(sa, 0, smix, false, tid);  __syncthreads();
    lin_multi(smix, 3, st2, false, tid); __syncthreads();
    lin_multi(st2, 12, smsg, true, tid); __syncthreads();
    /* order 1: sbuf = b2 (paths write atomically, no inner syncs) */
    path_pair3<1, true, 4, false>(sa, sa, 0, sbuf, tid);
    path_pair3<2, true, 4, false>(sa, sa, 1, sbuf, tid);
    path_pair3<6, true, 2, false>(sa, sa, 2, sbuf, tid);
    path_uvu3<0> (sa, o2u,        sbuf, tid);
    path_uvu3<4> (sa, o2u + 1024, sbuf, tid);
    path_uvu3<5> (sa, o2u + 2048, sbuf, tid);
    path_uvu3<9> (sa, o2u + 3072, sbuf, tid);
    path_uvu3<10>(sa, o2u + 4096, sbuf, tid);
    __syncthreads();
    lin_multi(sbuf, 6, smix, false, tid); __syncthreads();
    lin_multi(smix, 15, smsg, true, tid);
    for (int o = tid; o < NB * 288; o += 256) st2[o] = 0.f;
    __syncthreads();
    /* order 2 stage A: st2 = pair(a,a,o3a) */
    path_pair3<0, false, 4, false>(sa, sa, 3,  st2, tid);
    path_pair3<1, true,  4, false>(sa, sa, 4,  st2, tid);
    path_pair3<2, true,  4, false>(sa, sa, 5,  st2, tid);
    path_pair3<3, false, 4, false>(sa, sa, 6,  st2, tid);
    path_pair3<4, false, 2, false>(sa, sa, 7,  st2, tid);
    path_pair3<5, false, 2, false>(sa, sa, 8,  st2, tid);
    path_pair3<6, true,  2, false>(sa, sa, 9,  st2, tid);
    path_pair3<7, false, 4, false>(sa, sa, 10, st2, tid);
    path_pair3<8, false, 2, false>(sa, sa, 11, st2, tid);
    path_pair3<9, false, 2, true >(sa, sa, 12, st2, tid);
    path_pair3<10, false, 2, true>(sa, sa, 13, st2, tid);
    for (int o = tid; o < NB * 288; o += 256) sbuf[o] = 0.f;
    __syncthreads();
    /* order 2 stage B: sbuf = pair(st2, a, o3b) */
    path_pair3<0, false, 4, false>(st2, sa, 14, sbuf, tid);
    path_pair3<1, true,  4, false>(st2, sa, 15, sbuf, tid);
    path_pair3<2, true,  4, false>(st2, sa, 16, sbuf, tid);
    path_pair3<3, false, 4, false>(st2, sa, 17, sbuf, tid);
    path_pair3<4, false, 2, false>(st2, sa, 18, sbuf, tid);
    path_pair3<5, false, 2, false>(st2, sa, 19, sbuf, tid);
    path_pair3<6, true,  2, false>(st2, sa, 20, sbuf, tid);
    path_pair3<7, false, 4, false>(st2, sa, 21, sbuf, tid);
    path_pair3<8, false, 2, false>(st2, sa, 22, sbuf, tid);
    path_pair3<9, false, 2, true >(st2, sa, 23, sbuf, tid);
    path_pair3<10, false, 2, true>(st2, sa, 24, sbuf, tid);
    __syncthreads();
    lin_multi(sbuf, 9, smix, false, tid); __syncthreads();
    lin_multi(smix, 18, smsg, true, tid); __syncthreads();
    if (tid < NB * 32) {
        int n = tid >> 5, w = tid & 31;
        const float* r = nf + (z0 + n) * 32;
        float s = 0.f;
#pragma unroll 8
        for (int v = 0; v < 32; v++) s += r[v] * __ldg(selfw + v * 32 + w);
        smsg[n * 288 + w] += s * (1.f / SQM);
    }
    __syncthreads();
    for (int o = tid; o < NB * 288; o += 256) {
        int n = o / 288, idx = o - n * 288;
        int slot = idx >> 5, u = idx & 31;
        out[(z0 + n) * 288 + mergecol(u, slot)] = smsg[o];
    }
}

/* -------------------- launch ---------------------------------------- */
extern "C" void kernel_launch(void* const* d_in, const int* in_sizes, int n_in,
                              void* d_out, int out_size) {
    const float* nf    = (const float*)d_in[0];
    const int*   ei    = (const int*)d_in[1];
    const float* sh    = (const float*)d_in[2];
    const float* rad   = (const float*)d_in[3];
    const float* attr  = (const float*)d_in[4];
    const float* w1    = (const float*)d_in[5];
    const float* b1    = (const float*)d_in[6];
    const float* w2    = (const float*)d_in[7];
    const float* b2    = (const float*)d_in[8];
    const float* w3    = (const float*)d_in[9];
    const float* b3    = (const float*)d_in[10];
    const float* aw    = (const float*)d_in[11];
    const float* ab    = (const float*)d_in[12];
    const float* emb   = (const float*)d_in[13];
    const float* lino1 = (const float*)d_in[14];
    const float* o2w   = (const float*)d_in[15];
    const float* o2u   = (const float*)d_in[16];
    const float* o3a   = (const float*)d_in[17];
    const float* o3b   = (const float*)d_in[18];
    const float* mixw  = (const float*)d_in[19];
    const float* combw = (const float*)d_in[20];
    const float* selfw = (const float*)d_in[21];

    cudaFuncSetAttribute(mace_node, cudaFuncAttributeMaxDynamicSharedMemorySize, SMEM_NODE_BYTES);

    mace_init<<<(N_NODES * 288 + 255) / 256, 256>>>(aw, ab, o2w, o3a, o3b, lino1, mixw, combw);
    mace_front<<<8000 + 625, 512>>>(ei, rad, attr, w1, b1, w2, b2, w3, b3, nf, emb);
    mace_edge_gemm<<<N_EDGES / 64, 256>>>(ei, sh);
    mace_node<<<N_NODES / NB, 256, SMEM_NODE_BYTES>>>(nf, o2u, selfw, (float*)d_out);
}